// round 8
// baseline (speedup 1.0000x reference)
#include <cuda_runtime.h>
#include <cuda_bf16.h>
#include <cstdint>

using bf16 = __nv_bfloat16;

#define B_  32
#define S_  41
#define T_  41
#define H_  1024
#define V_  16384
#define G_  4096
#define NA_ 5120   // combined q(1024) + ghh(4096)
#define TB_ 1312   // T_*B_
#define NB_ 128    // persistent grid size (<= SM count, all co-resident)

// output layout (flattened concat of reference return values, fp32)
#define OUT_DEC  0ull
#define OUT_HF   21495808ull
#define OUT_CF   21528576ull
#define OUT_ATTN 21561344ull

// ------------------------- device scratch (static, no allocs) -------------------------
__device__ bf16  g_enc_hi[TB_ * H_];
__device__ bf16  g_enc_lo[TB_ * H_];
__device__ float g_encT[B_ * H_ * S_];          // enc transposed [b,h,s]
__device__ bf16  g_Wk_hi[H_ * H_];
__device__ bf16  g_Wk_lo[H_ * H_];
__device__ bf16  g_Wqhh_hi[NA_ * H_];           // rows 0..1023 = Wq; 1024..5119 = Whh
__device__ bf16  g_Wqhh_lo[NA_ * H_];
__device__ bf16  g_Wx_hi[G_ * H_];              // Wih[:, 0:1024]   (x part)
__device__ bf16  g_Wx_lo[G_ * H_];
__device__ bf16  g_Wc_hi[G_ * H_];              // Wih[:, 1024:2048] (ctx part)
__device__ bf16  g_Wc_lo[G_ * H_];
__device__ bf16  g_Wout_bf[(size_t)V_ * H_];
__device__ bf16  g_X_hi[TB_ * H_];
__device__ bf16  g_X_lo[TB_ * H_];
__device__ float g_keys[TB_ * H_];
__device__ float g_gates_pre[(size_t)TB_ * G_]; // X@Wx^T + bih + bhh
__device__ float g_qghh[B_ * NA_];              // per b: [q(1024) | h@Whh^T(4096)]
__device__ bf16  g_ctxh_hi[B_ * 2 * H_];        // per b: [ctx(1024) | h(1024)]
__device__ bf16  g_ctxh_lo[B_ * 2 * H_];
__device__ float g_h[2][B_ * H_];
__device__ float g_c[2][B_ * H_];
__device__ bf16  g_Hbf[TB_ * H_];
__device__ float g_bsum[G_];
__device__ float g_bA[NA_];                     // [bq | zeros]
__device__ unsigned g_barc;                     // grid-barrier arrive counter
__device__ volatile unsigned g_barg;            // grid-barrier generation

__device__ __forceinline__ void split_bf(float v, bf16& hi, bf16& lo) {
    bf16 h = __float2bfloat16(v);
    hi = h;
    lo = __float2bfloat16(v - __bfloat162float(h));
}

// ------------------------- small prep kernels -------------------------
__global__ void k_cvt(const float* __restrict__ s, bf16* __restrict__ d, int n) {
    for (int i = blockIdx.x * blockDim.x + threadIdx.x; i < n; i += gridDim.x * blockDim.x)
        d[i] = __float2bfloat16(s[i]);
}

__global__ void k_cvt2(const float* __restrict__ s, bf16* __restrict__ hi, bf16* __restrict__ lo, int n) {
    for (int i = blockIdx.x * blockDim.x + threadIdx.x; i < n; i += gridDim.x * blockDim.x)
        split_bf(s[i], hi[i], lo[i]);
}

__global__ void k_wqhh(const float* __restrict__ Wq, const float* __restrict__ Whh) {
    for (int i = blockIdx.x * blockDim.x + threadIdx.x; i < NA_ * H_; i += gridDim.x * blockDim.x) {
        int n = i >> 10, k = i & 1023;
        float v = (n < 1024) ? Wq[(size_t)n * H_ + k] : Whh[(size_t)(n - 1024) * H_ + k];
        split_bf(v, g_Wqhh_hi[i], g_Wqhh_lo[i]);
    }
}

__global__ void k_cvt_wx(const float* __restrict__ Wih) {
    for (int i = blockIdx.x * blockDim.x + threadIdx.x; i < G_ * H_; i += gridDim.x * blockDim.x) {
        int n = i >> 10, k = i & 1023;
        split_bf(Wih[(size_t)n * 2048 + k], g_Wx_hi[i], g_Wx_lo[i]);
    }
}

__global__ void k_wc(const float* __restrict__ Wih) {
    for (int i = blockIdx.x * blockDim.x + threadIdx.x; i < G_ * H_; i += gridDim.x * blockDim.x) {
        int n = i >> 10, k = i & 1023;
        split_bf(Wih[(size_t)n * 2048 + 1024 + k], g_Wc_hi[i], g_Wc_lo[i]);
    }
}

__global__ void k_bias(const float* __restrict__ bih, const float* __restrict__ bhh,
                       const float* __restrict__ bq) {
    int i = blockIdx.x * blockDim.x + threadIdx.x;
    if (i < G_) g_bsum[i] = bih[i] + bhh[i];
    if (i < NA_) g_bA[i] = (i < H_) ? bq[i] : 0.f;
}

__global__ void k_init(const float* __restrict__ ehid) {
    int i = blockIdx.x * blockDim.x + threadIdx.x;
    if (i == 0) { g_barc = 0; g_barg = 0; }
    if (i < B_ * H_) {
        float h = ehid[i];
        g_c[0][i] = 0.f;
        g_h[0][i] = h;
        int b = i >> 10, j = i & 1023;
        split_bf(h, g_ctxh_hi[b * 2048 + 1024 + j], g_ctxh_lo[b * 2048 + 1024 + j]);
    }
}

// NOTE: target_tensor is int32 on the wire (JAX downcasts int64 without x64 mode).
__global__ void k_gather(const float* __restrict__ emb, const int* __restrict__ tgt) {
    int r = blockIdx.x;             // r = t*32 + b
    int t = r >> 5, b = r & 31;
    int tok = (t == 0) ? 0 : tgt[b * 41 + (t - 1)];
    tok &= (V_ - 1);                // defensive: never fault on bad data
    const float* src = emb + (size_t)tok * H_;
    for (int h = threadIdx.x; h < H_; h += blockDim.x)
        split_bf(src[h], g_X_hi[(size_t)r * H_ + h], g_X_lo[(size_t)r * H_ + h]);
}

__global__ void k_transpose_enc(const float* __restrict__ enc) {
    int b = blockIdx.x;
    const float* src = enc + (size_t)b * S_ * H_;
    float* dst = g_encT + (size_t)b * H_ * S_;
    for (int i = threadIdx.x; i < S_ * H_; i += blockDim.x) {
        int s = i >> 10, h = i & 1023;
        dst[h * S_ + s] = src[i];
    }
}

// ------------------------- MMA primitive -------------------------
__device__ __forceinline__ void mma16816(float* c, const uint32_t* a, const uint32_t* b) {
    asm volatile(
        "mma.sync.aligned.m16n8k16.row.col.f32.bf16.bf16.f32 "
        "{%0,%1,%2,%3}, {%4,%5,%6,%7}, {%8,%9}, {%0,%1,%2,%3};"
        : "+f"(c[0]), "+f"(c[1]), "+f"(c[2]), "+f"(c[3])
        : "r"(a[0]), "r"(a[1]), "r"(a[2]), "r"(a[3]), "r"(b[0]), "r"(b[1]));
}

// ---------- single-bf16 GEMM: C = A @ B^T (+bias); REMAP: row r=t*32+b -> out row b*T+t ----------
template <int WM, int WN, int NW, bool REMAP>
__global__ void __launch_bounds__(32 * NW)
k_gemm(const bf16* __restrict__ A, int lda,
       const bf16* __restrict__ B, int ldb,
       float* __restrict__ C, int ldc,
       const float* __restrict__ bias,
       int M, int N, int K) {
    const int lane = threadIdx.x & 31, warp = threadIdx.x >> 5;
    const int g = lane >> 2, tg = lane & 3;
    const int m0 = blockIdx.x * (16 * WM);
    const int n0 = blockIdx.y * (8 * WN * NW) + warp * (8 * WN);

    float acc[WM][WN][4];
#pragma unroll
    for (int i = 0; i < WM; i++)
#pragma unroll
        for (int j = 0; j < WN; j++)
#pragma unroll
            for (int q = 0; q < 4; q++) acc[i][j][q] = 0.f;

#pragma unroll 2
    for (int k0 = 0; k0 < K; k0 += 16) {
        uint32_t a[WM][4];
#pragma unroll
        for (int i = 0; i < WM; i++) {
            int r0 = m0 + 16 * i + g;
            int r1 = r0 + 8;
            int ra0 = (r0 < M) ? r0 : (M - 1);
            int ra1 = (r1 < M) ? r1 : (M - 1);
            const uint32_t* p0 = reinterpret_cast<const uint32_t*>(A + (size_t)ra0 * lda + k0);
            const uint32_t* p1 = reinterpret_cast<const uint32_t*>(A + (size_t)ra1 * lda + k0);
            a[i][0] = (r0 < M) ? p0[tg]     : 0u;
            a[i][2] = (r0 < M) ? p0[tg + 4] : 0u;
            a[i][1] = (r1 < M) ? p1[tg]     : 0u;
            a[i][3] = (r1 < M) ? p1[tg + 4] : 0u;
        }
        uint32_t b[WN][2];
#pragma unroll
        for (int j = 0; j < WN; j++) {
            int n = n0 + 8 * j + g;
            const uint32_t* pb = reinterpret_cast<const uint32_t*>(B + (size_t)n * ldb + k0);
            b[j][0] = pb[tg];
            b[j][1] = pb[tg + 4];
        }
#pragma unroll
        for (int i = 0; i < WM; i++)
#pragma unroll
            for (int j = 0; j < WN; j++) mma16816(acc[i][j], a[i], b[j]);
    }

#pragma unroll
    for (int i = 0; i < WM; i++) {
        int r0 = m0 + 16 * i + g;
        int r1 = r0 + 8;
        size_t or0 = REMAP ? ((size_t)(r0 & 31) * T_ + (r0 >> 5)) : (size_t)r0;
        size_t or1 = REMAP ? ((size_t)(r1 & 31) * T_ + (r1 >> 5)) : (size_t)r1;
#pragma unroll
        for (int j = 0; j < WN; j++) {
            int c0 = n0 + 8 * j + 2 * tg;
            float v0 = acc[i][j][0], v1 = acc[i][j][1], v2 = acc[i][j][2], v3 = acc[i][j][3];
            if (bias) {
                float bb0 = bias[c0], bb1 = bias[c0 + 1];
                v0 += bb0; v1 += bb1; v2 += bb0; v3 += bb1;
            }
            if (r0 < M) { C[or0 * ldc + c0] = v0; C[or0 * ldc + c0 + 1] = v1; }
            if (r1 < M) { C[or1 * ldc + c0] = v2; C[or1 * ldc + c0 + 1] = v3; }
        }
    }
}

// --------------- split-bf16 GEMM (~fp32 precision): C = A @ B^T (+bias) ---------------
template <int WM, int WN, int NW>
__global__ void __launch_bounds__(32 * NW)
k_gemm2(const bf16* __restrict__ Ah, const bf16* __restrict__ Al, int lda,
        const bf16* __restrict__ Bh, const bf16* __restrict__ Bl, int ldb,
        float* __restrict__ C, int ldc,
        const float* __restrict__ bias,
        int M, int N, int K) {
    const int lane = threadIdx.x & 31, warp = threadIdx.x >> 5;
    const int g = lane >> 2, tg = lane & 3;
    const int m0 = blockIdx.x * (16 * WM);
    const int n0 = blockIdx.y * (8 * WN * NW) + warp * (8 * WN);

    float acc[WM][WN][4];
#pragma unroll
    for (int i = 0; i < WM; i++)
#pragma unroll
        for (int j = 0; j < WN; j++)
#pragma unroll
            for (int q = 0; q < 4; q++) acc[i][j][q] = 0.f;

#pragma unroll 2
    for (int k0 = 0; k0 < K; k0 += 16) {
        uint32_t ah[WM][4], al[WM][4];
#pragma unroll
        for (int i = 0; i < WM; i++) {
            int r0 = m0 + 16 * i + g;
            int r1 = r0 + 8;
            int ra0 = (r0 < M) ? r0 : (M - 1);
            int ra1 = (r1 < M) ? r1 : (M - 1);
            const uint32_t* ph0 = reinterpret_cast<const uint32_t*>(Ah + (size_t)ra0 * lda + k0);
            const uint32_t* ph1 = reinterpret_cast<const uint32_t*>(Ah + (size_t)ra1 * lda + k0);
            const uint32_t* pl0 = reinterpret_cast<const uint32_t*>(Al + (size_t)ra0 * lda + k0);
            const uint32_t* pl1 = reinterpret_cast<const uint32_t*>(Al + (size_t)ra1 * lda + k0);
            ah[i][0] = (r0 < M) ? ph0[tg]     : 0u;
            ah[i][2] = (r0 < M) ? ph0[tg + 4] : 0u;
            ah[i][1] = (r1 < M) ? ph1[tg]     : 0u;
            ah[i][3] = (r1 < M) ? ph1[tg + 4] : 0u;
            al[i][0] = (r0 < M) ? pl0[tg]     : 0u;
            al[i][2] = (r0 < M) ? pl0[tg + 4] : 0u;
            al[i][1] = (r1 < M) ? pl1[tg]     : 0u;
            al[i][3] = (r1 < M) ? pl1[tg + 4] : 0u;
        }
        uint32_t bh[WN][2], bl[WN][2];
#pragma unroll
        for (int j = 0; j < WN; j++) {
            int n = n0 + 8 * j + g;
            const uint32_t* pbh = reinterpret_cast<const uint32_t*>(Bh + (size_t)n * ldb + k0);
            const uint32_t* pbl = reinterpret_cast<const uint32_t*>(Bl + (size_t)n * ldb + k0);
            bh[j][0] = pbh[tg];
            bh[j][1] = pbh[tg + 4];
            bl[j][0] = pbl[tg];
            bl[j][1] = pbl[tg + 4];
        }
#pragma unroll
        for (int i = 0; i < WM; i++)
#pragma unroll
            for (int j = 0; j < WN; j++) {
                mma16816(acc[i][j], ah[i], bh[j]);
                mma16816(acc[i][j], ah[i], bl[j]);
                mma16816(acc[i][j], al[i], bh[j]);
            }
    }

#pragma unroll
    for (int i = 0; i < WM; i++) {
        int r0 = m0 + 16 * i + g;
        int r1 = r0 + 8;
#pragma unroll
        for (int j = 0; j < WN; j++) {
            int c0 = n0 + 8 * j + 2 * tg;
            float v0 = acc[i][j][0], v1 = acc[i][j][1], v2 = acc[i][j][2], v3 = acc[i][j][3];
            if (bias) {
                float bb0 = bias[c0], bb1 = bias[c0 + 1];
                v0 += bb0; v1 += bb1; v2 += bb0; v3 += bb1;
            }
            if (r0 < M) { C[(size_t)r0 * ldc + c0] = v0; C[(size_t)r0 * ldc + c0 + 1] = v1; }
            if (r1 < M) { C[(size_t)r1 * ldc + c0] = v2; C[(size_t)r1 * ldc + c0 + 1] = v3; }
        }
    }
}

// ==================== persistent recurrence kernel (whole 41-step loop) ====================
__device__ __forceinline__ void gbar() {
    __syncthreads();
    if (threadIdx.x == 0) {
        __threadfence();
        unsigned gen = g_barg;
        if (atomicAdd(&g_barc, 1u) == NB_ - 1u) {
            g_barc = 0;
            __threadfence();
            g_barg = gen + 1u;
        } else {
            while (g_barg == gen) { }
            __threadfence();
        }
    }
    __syncthreads();
}

__global__ void __launch_bounds__(256) k_loop(const float* __restrict__ Vw,
                                              const float* __restrict__ bV,
                                              float* __restrict__ out) {
    __shared__ union {
        struct { float sq[H_]; float sv[H_]; float ssc[48]; } at;
        float sg[32][33];
    } sm;

    const int tid = threadIdx.x, lane = tid & 31, warp = tid >> 5;
    const int g = lane >> 2, tg = lane & 3;

    for (int t = 0; t < T_; t++) {
        // ---------------- Phase A: qghh = h @ [Wq|Whh]^T + bA  (32 x 5120, K=1024) ----------------
        {
            const int gw = blockIdx.x * 8 + warp;     // 1024 warps; 640 tiles
            if (gw < NA_ / 8) {
                const int n0 = gw * 8;
                float acc[2][4] = {{0.f,0.f,0.f,0.f},{0.f,0.f,0.f,0.f}};
                const bf16* Bh = g_Wqhh_hi + (size_t)(n0 + g) * H_;
                const bf16* Bl = g_Wqhh_lo + (size_t)(n0 + g) * H_;
#pragma unroll 4
                for (int k0 = 0; k0 < H_; k0 += 16) {
                    uint32_t bh[2], bl[2];
                    const uint32_t* pbh = reinterpret_cast<const uint32_t*>(Bh + k0);
                    const uint32_t* pbl = reinterpret_cast<const uint32_t*>(Bl + k0);
                    bh[0] = pbh[tg]; bh[1] = pbh[tg + 4];
                    bl[0] = pbl[tg]; bl[1] = pbl[tg + 4];
#pragma unroll
                    for (int i = 0; i < 2; i++) {
                        const int r0 = i * 16 + g, r1 = r0 + 8;
                        uint32_t ah[4], al[4];
                        const uint32_t* ph0 = reinterpret_cast<const uint32_t*>(g_ctxh_hi + r0 * 2048 + H_ + k0);
                        const uint32_t* ph1 = reinterpret_cast<const uint32_t*>(g_ctxh_hi + r1 * 2048 + H_ + k0);
                        const uint32_t* pl0 = reinterpret_cast<const uint32_t*>(g_ctxh_lo + r0 * 2048 + H_ + k0);
                        const uint32_t* pl1 = reinterpret_cast<const uint32_t*>(g_ctxh_lo + r1 * 2048 + H_ + k0);
                        ah[0] = ph0[tg]; ah[2] = ph0[tg + 4];
                        ah[1] = ph1[tg]; ah[3] = ph1[tg + 4];
                        al[0] = pl0[tg]; al[2] = pl0[tg + 4];
                        al[1] = pl1[tg]; al[3] = pl1[tg + 4];
                        mma16816(acc[i], ah, bh);
                        mma16816(acc[i], ah, bl);
                        mma16816(acc[i], al, bh);
                    }
                }
                const int c0 = n0 + 2 * tg;
                const float b0 = g_bA[c0], b1 = g_bA[c0 + 1];
#pragma unroll
                for (int i = 0; i < 2; i++) {
                    const int r0 = i * 16 + g, r1 = r0 + 8;
                    g_qghh[r0 * NA_ + c0]     = acc[i][0] + b0;
                    g_qghh[r0 * NA_ + c0 + 1] = acc[i][1] + b1;
                    g_qghh[r1 * NA_ + c0]     = acc[i][2] + b0;
                    g_qghh[r1 * NA_ + c0 + 1] = acc[i][3] + b1;
                }
            }
        }
        gbar();

        // ---------------- Phase B: attention (32 active blocks, b = blockIdx.x) ----------------
        if (blockIdx.x < B_) {
            const int b = blockIdx.x;
            for (int i = tid; i < H_; i += 256) { sm.at.sq[i] = g_qghh[b * NA_ + i]; sm.at.sv[i] = Vw[i]; }
            __syncthreads();

            for (int s = warp; s < S_; s += 8) {
                const float* kp = g_keys + ((size_t)b * S_ + s) * H_;
                float a = 0.f;
                for (int h = lane; h < H_; h += 32)
                    a += tanhf(sm.at.sq[h] + kp[h]) * sm.at.sv[h];
#pragma unroll
                for (int o = 16; o; o >>= 1) a += __shfl_xor_sync(0xffffffffu, a, o);
                if (lane == 0) sm.at.ssc[s] = a + bV[0];
            }
            __syncthreads();

            if (warp == 0) {
                float v0 = sm.at.ssc[lane];
                float v1 = (lane < S_ - 32) ? sm.at.ssc[lane + 32] : -INFINITY;
                float m = fmaxf(v0, v1);
#pragma unroll
                for (int o = 16; o; o >>= 1) m = fmaxf(m, __shfl_xor_sync(0xffffffffu, m, o));
                float e0 = expf(v0 - m);
                float e1 = (lane < S_ - 32) ? expf(v1 - m) : 0.f;
                float s = e0 + e1;
#pragma unroll
                for (int o = 16; o; o >>= 1) s += __shfl_xor_sync(0xffffffffu, s, o);
                float inv = 1.f / s;
                float w0 = e0 * inv;
                sm.at.ssc[lane] = w0;
                out[OUT_ATTN + ((size_t)b * T_ + t) * S_ + lane] = w0;
                if (lane < S_ - 32) {
                    float w1 = e1 * inv;
                    sm.at.ssc[lane + 32] = w1;
                    out[OUT_ATTN + ((size_t)b * T_ + t) * S_ + lane + 32] = w1;
                }
            }
            __syncthreads();

            for (int h = tid; h < H_; h += 256) {
                const float* ep = g_encT + ((size_t)b * H_ + h) * S_;
                float a = 0.f;
#pragma unroll
                for (int s = 0; s < S_; s++) a += sm.at.ssc[s] * ep[s];
                split_bf(a, g_ctxh_hi[b * 2048 + h], g_ctxh_lo[b * 2048 + h]);
            }
        }
        gbar();

        // ---------------- Phase C: gates(ctx) + LSTM update (all 128 blocks) ----------------
        {
            const int j0 = blockIdx.x * 8;
            const int qg = warp >> 1, mh = warp & 1;
            const int m0 = mh * 16;
            const int ng = qg * 1024 + j0;

            float acc[4] = {0.f, 0.f, 0.f, 0.f};
            const int r0 = m0 + g, r1 = r0 + 8;
            const bf16* Ah0 = g_ctxh_hi + r0 * 2048;
            const bf16* Ah1 = g_ctxh_hi + r1 * 2048;
            const bf16* Al0 = g_ctxh_lo + r0 * 2048;
            const bf16* Al1 = g_ctxh_lo + r1 * 2048;
            const bf16* Bh = g_Wc_hi + (size_t)(ng + g) * H_;
            const bf16* Bl = g_Wc_lo + (size_t)(ng + g) * H_;

#pragma unroll 4
            for (int k0 = 0; k0 < H_; k0 += 16) {
                uint32_t ah[4], al[4], bh[2], bl[2];
                const uint32_t* ph0 = reinterpret_cast<const uint32_t*>(Ah0 + k0);
                const uint32_t* ph1 = reinterpret_cast<const uint32_t*>(Ah1 + k0);
                const uint32_t* pl0 = reinterpret_cast<const uint32_t*>(Al0 + k0);
                const uint32_t* pl1 = reinterpret_cast<const uint32_t*>(Al1 + k0);
                const uint32_t* pbh = reinterpret_cast<const uint32_t*>(Bh + k0);
                const uint32_t* pbl = reinterpret_cast<const uint32_t*>(Bl + k0);
                ah[0] = ph0[tg]; ah[2] = ph0[tg + 4];
                ah[1] = ph1[tg]; ah[3] = ph1[tg + 4];
                al[0] = pl0[tg]; al[2] = pl0[tg + 4];
                al[1] = pl1[tg]; al[3] = pl1[tg + 4];
                bh[0] = pbh[tg]; bh[1] = pbh[tg + 4];
                bl[0] = pbl[tg]; bl[1] = pbl[tg + 4];
                mma16816(acc, ah, bh);
                mma16816(acc, ah, bl);
                mma16816(acc, al, bh);
            }

            {
                const float* gpre = g_gates_pre + (size_t)t * B_ * G_;
                int c0 = 2 * tg;
                int gc = ng + c0;
                sm.sg[r0][qg * 8 + c0]     = acc[0] + gpre[(size_t)r0 * G_ + gc]     + g_qghh[r0 * NA_ + H_ + gc];
                sm.sg[r0][qg * 8 + c0 + 1] = acc[1] + gpre[(size_t)r0 * G_ + gc + 1] + g_qghh[r0 * NA_ + H_ + gc + 1];
                sm.sg[r1][qg * 8 + c0]     = acc[2] + gpre[(size_t)r1 * G_ + gc]     + g_qghh[r1 * NA_ + H_ + gc];
                sm.sg[r1][qg * 8 + c0 + 1] = acc[3] + gpre[(size_t)r1 * G_ + gc + 1] + g_qghh[r1 * NA_ + H_ + gc + 1];
            }
            __syncthreads();

            const int b = tid >> 3, jj = tid & 7;
            const int j = j0 + jj;
            float ig = 1.f / (1.f + expf(-sm.sg[b][jj]));
            float fg = 1.f / (1.f + expf(-sm.sg[b][8 + jj]));
            float gg = tanhf(sm.sg[b][16 + jj]);
            float og = 1.f / (1.f + expf(-sm.sg[b][24 + jj]));
            int par = t & 1;
            int idx = b * H_ + j;
            float c = fg * g_c[par][idx] + ig * gg;
            float h = og * tanhf(c);
            g_c[par ^ 1][idx] = c;
            g_h[par ^ 1][idx] = h;
            split_bf(h, g_ctxh_hi[b * 2048 + H_ + j], g_ctxh_lo[b * 2048 + H_ + j]);
            g_Hbf[(size_t)(t * B_ + b) * H_ + j] = __float2bfloat16(h);
        }
        gbar();
    }
}

// ------------------------- in-place log-softmax over V per output row -------------------------
__global__ void __launch_bounds__(256) k_logsoftmax(float* __restrict__ out) {
    __shared__ float red[8];
    __shared__ float bc;
    const int r = blockIdx.x;
    float* x = out + OUT_DEC + (size_t)r * V_;
    const int tid = threadIdx.x, lane = tid & 31, warp = tid >> 5;

    float m = -INFINITY;
    for (int v = tid; v < V_; v += 256) m = fmaxf(m, x[v]);
#pragma unroll
    for (int o2 = 16; o2; o2 >>= 1) m = fmaxf(m, __shfl_xor_sync(0xffffffffu, m, o2));
    if (lane == 0) red[warp] = m;
    __syncthreads();
    if (tid == 0) {
        float mm = red[0];
#pragma unroll
        for (int w = 1; w < 8; w++) mm = fmaxf(mm, red[w]);
        bc = mm;
    }
    __syncthreads();
    m = bc;

    float s = 0.f;
    for (int v = tid; v < V_; v += 256) s += expf(x[v] - m);
#pragma unroll
    for (int o2 = 16; o2; o2 >>= 1) s += __shfl_xor_sync(0xffffffffu, s, o2);
    __syncthreads();
    if (lane == 0) red[warp] = s;
    __syncthreads();
    if (tid == 0) {
        float ss = 0.f;
#pragma unroll
        for (int w = 0; w < 8; w++) ss += red[w];
        bc = m + logf(ss);
    }
    __syncthreads();
    float ls = bc;

    for (int v = tid; v < V_; v += 256) x[v] -= ls;
}

// ------------------------- final state copy -------------------------
__global__ void __launch_bounds__(256) k_final(float* __restrict__ out) {
    int i = blockIdx.x * blockDim.x + threadIdx.x;
    if (i < B_ * H_) {
        out[OUT_HF + i] = g_h[1][i];
        out[OUT_CF + i] = g_c[1][i];
    }
}

// ------------------------- launch -------------------------
extern "C" void kernel_launch(void* const* d_in, const int* in_sizes, int n_in,
                              void* d_out, int out_size) {
    (void)in_sizes; (void)n_in; (void)out_size;
    const float* enc  = (const float*)d_in[0];
    const float* ehid = (const float*)d_in[1];
    const int*   tgt  = (const int*)d_in[2];
    const float* emb  = (const float*)d_in[3];
    const float* Wq   = (const float*)d_in[4];
    const float* bq   = (const float*)d_in[5];
    const float* Wk   = (const float*)d_in[6];
    const float* bk   = (const float*)d_in[7];
    const float* Vw   = (const float*)d_in[8];
    const float* bV   = (const float*)d_in[9];
    const float* Wih  = (const float*)d_in[10];
    const float* Whh  = (const float*)d_in[11];
    const float* bih  = (const float*)d_in[12];
    const float* bhh  = (const float*)d_in[13];
    const float* Wout = (const float*)d_in[14];
    const float* bout = (const float*)d_in[15];
    float* out = (float*)d_out;

    void *p_enc_hi, *p_enc_lo, *p_Wk_hi, *p_Wk_lo, *p_Wx_hi, *p_Wx_lo,
         *p_Wout, *p_X_hi, *p_X_lo, *p_keys, *p_gpre, *p_Hbf, *p_bsum;
    cudaGetSymbolAddress(&p_enc_hi, g_enc_hi);
    cudaGetSymbolAddress(&p_enc_lo, g_enc_lo);
    cudaGetSymbolAddress(&p_Wk_hi, g_Wk_hi);
    cudaGetSymbolAddress(&p_Wk_lo, g_Wk_lo);
    cudaGetSymbolAddress(&p_Wx_hi, g_Wx_hi);
    cudaGetSymbolAddress(&p_Wx_lo, g_Wx_lo);
    cudaGetSymbolAddress(&p_Wout, g_Wout_bf);
    cudaGetSymbolAddress(&p_X_hi, g_X_hi);
    cudaGetSymbolAddress(&p_X_lo, g_X_lo);
    cudaGetSymbolAddress(&p_keys, g_keys);
    cudaGetSymbolAddress(&p_gpre, g_gates_pre);
    cudaGetSymbolAddress(&p_Hbf, g_Hbf);
    cudaGetSymbolAddress(&p_bsum, g_bsum);

    // prep
    k_cvt2<<<2048, 256>>>(enc, (bf16*)p_enc_hi, (bf16*)p_enc_lo, TB_ * H_);
    k_transpose_enc<<<B_, 256>>>(enc);
    k_cvt2<<<1024, 256>>>(Wk, (bf16*)p_Wk_hi, (bf16*)p_Wk_lo, H_ * H_);
    k_cvt<<<4096, 256>>>(Wout, (bf16*)p_Wout, V_ * H_);
    k_wqhh<<<4096, 256>>>(Wq, Whh);
    k_cvt_wx<<<4096, 256>>>(Wih);
    k_wc<<<4096, 256>>>(Wih);
    k_bias<<<20, 256>>>(bih, bhh, bq);
    k_init<<<128, 256>>>(ehid);
    k_gather<<<TB_, 256>>>(emb, tgt);

    // hoisted GEMMs (split precision)
    {   // keys_proj = enc @ Wk^T + bk : [1312,1024]
        dim3 grid((TB_ + 63) / 64, H_ / 128);
        k_gemm2<4, 2, 8><<<grid, 256>>>((const bf16*)p_enc_hi, (const bf16*)p_enc_lo, H_,
                                        (const bf16*)p_Wk_hi, (const bf16*)p_Wk_lo, H_,
                                        (float*)p_keys, H_, bk, TB_, H_, H_);
    }
    {   // gates_pre = X @ Wx^T + (bih+bhh) : [1312,4096]
        dim3 grid((TB_ + 63) / 64, G_ / 128);
        k_gemm2<4, 2, 8><<<grid, 256>>>((const bf16*)p_X_hi, (const bf16*)p_X_lo, H_,
                                        (const bf16*)p_Wx_hi, (const bf16*)p_Wx_lo, H_,
                                        (float*)p_gpre, G_, (const float*)p_bsum, TB_, G_, H_);
    }

    // entire 41-step recurrence in ONE persistent kernel
    k_loop<<<NB_, 256>>>(Vw, bV, out);

    {   // logits -> directly into out[OUT_DEC] at [b,t,:] via remap epilogue
        dim3 grid((TB_ + 63) / 64, V_ / 128);
        k_gemm<4, 2, 8, true><<<grid, 256>>>((const bf16*)p_Hbf, H_, (const bf16*)p_Wout, H_,
                                             out + OUT_DEC, V_, bout, TB_, V_, H_);
    }
    k_logsoftmax<<<TB_, 256>>>(out);
    k_final<<<128, 256>>>(out);
}

// round 9
// speedup vs baseline: 1.0757x; 1.0757x over previous
#include <cuda_runtime.h>
#include <cuda_bf16.h>
#include <cstdint>

using bf16 = __nv_bfloat16;

#define B_  32
#define S_  41
#define T_  41
#define H_  1024
#define V_  16384
#define G_  4096
#define NA_ 5120   // combined q(1024) + ghh(4096)
#define TB_ 1312   // T_*B_
#define KS_ 4      // split-K factor for loop GEMMs
#define KC_ (H_ / KS_)   // 256

// output layout (flattened concat of reference return values, fp32)
#define OUT_DEC  0ull
#define OUT_HF   21495808ull
#define OUT_CF   21528576ull
#define OUT_ATTN 21561344ull

// ------------------------- device scratch (static, no allocs) -------------------------
__device__ bf16  g_enc_hi[TB_ * H_];
__device__ bf16  g_enc_lo[TB_ * H_];
__device__ float g_encT[B_ * H_ * S_];          // enc transposed [b,h,s]
__device__ bf16  g_Wk_hi[H_ * H_];
__device__ bf16  g_Wk_lo[H_ * H_];
__device__ bf16  g_Wqhh_hi[NA_ * H_];           // rows 0..1023 = Wq; 1024..5119 = Whh
__device__ bf16  g_Wqhh_lo[NA_ * H_];
__device__ bf16  g_Wx_hi[G_ * H_];              // Wih[:, 0:1024]   (x part)
__device__ bf16  g_Wx_lo[G_ * H_];
__device__ bf16  g_Wc_hi[G_ * H_];              // Wih[:, 1024:2048] (ctx part)
__device__ bf16  g_Wc_lo[G_ * H_];
__device__ bf16  g_Wout_bf[(size_t)V_ * H_];
__device__ bf16  g_X_hi[TB_ * H_];
__device__ bf16  g_X_lo[TB_ * H_];
__device__ float g_keys[TB_ * H_];
__device__ float g_gates_pre[(size_t)TB_ * G_]; // X@Wx^T + bih + bhh
__device__ float g_qA[KS_ * B_ * NA_];          // split-K partials of h@[Wq|Whh]^T
__device__ float g_gp[KS_ * B_ * G_];           // split-K partials of ctx@Wc^T
__device__ bf16  g_ctxh_hi[B_ * 2 * H_];        // per b: [ctx(1024) | h(1024)]
__device__ bf16  g_ctxh_lo[B_ * 2 * H_];
__device__ float g_h[2][B_ * H_];
__device__ float g_c[2][B_ * H_];
__device__ bf16  g_Hbf[TB_ * H_];
__device__ float g_bsum[G_];

__device__ __forceinline__ void split_bf(float v, bf16& hi, bf16& lo) {
    bf16 h = __float2bfloat16(v);
    hi = h;
    lo = __float2bfloat16(v - __bfloat162float(h));
}

// ------------------------- small prep kernels -------------------------
__global__ void k_cvt(const float* __restrict__ s, bf16* __restrict__ d, int n) {
    for (int i = blockIdx.x * blockDim.x + threadIdx.x; i < n; i += gridDim.x * blockDim.x)
        d[i] = __float2bfloat16(s[i]);
}

__global__ void k_cvt2(const float* __restrict__ s, bf16* __restrict__ hi, bf16* __restrict__ lo, int n) {
    for (int i = blockIdx.x * blockDim.x + threadIdx.x; i < n; i += gridDim.x * blockDim.x)
        split_bf(s[i], hi[i], lo[i]);
}

__global__ void k_wqhh(const float* __restrict__ Wq, const float* __restrict__ Whh) {
    for (int i = blockIdx.x * blockDim.x + threadIdx.x; i < NA_ * H_; i += gridDim.x * blockDim.x) {
        int n = i >> 10, k = i & 1023;
        float v = (n < 1024) ? Wq[(size_t)n * H_ + k] : Whh[(size_t)(n - 1024) * H_ + k];
        split_bf(v, g_Wqhh_hi[i], g_Wqhh_lo[i]);
    }
}

__global__ void k_cvt_wx(const float* __restrict__ Wih) {
    for (int i = blockIdx.x * blockDim.x + threadIdx.x; i < G_ * H_; i += gridDim.x * blockDim.x) {
        int n = i >> 10, k = i & 1023;
        split_bf(Wih[(size_t)n * 2048 + k], g_Wx_hi[i], g_Wx_lo[i]);
    }
}

__global__ void k_wc(const float* __restrict__ Wih) {
    for (int i = blockIdx.x * blockDim.x + threadIdx.x; i < G_ * H_; i += gridDim.x * blockDim.x) {
        int n = i >> 10, k = i & 1023;
        split_bf(Wih[(size_t)n * 2048 + 1024 + k], g_Wc_hi[i], g_Wc_lo[i]);
    }
}

__global__ void k_bias(const float* __restrict__ bih, const float* __restrict__ bhh) {
    int i = blockIdx.x * blockDim.x + threadIdx.x;
    if (i < G_) g_bsum[i] = bih[i] + bhh[i];
}

__global__ void k_init(const float* __restrict__ ehid) {
    int i = blockIdx.x * blockDim.x + threadIdx.x;
    if (i < B_ * H_) {
        float h = ehid[i];
        g_c[0][i] = 0.f;
        g_h[0][i] = h;
        int b = i >> 10, j = i & 1023;
        split_bf(h, g_ctxh_hi[b * 2048 + 1024 + j], g_ctxh_lo[b * 2048 + 1024 + j]);
    }
}

// NOTE: target_tensor is int32 on the wire (JAX downcasts int64 without x64 mode).
__global__ void k_gather(const float* __restrict__ emb, const int* __restrict__ tgt) {
    int r = blockIdx.x;             // r = t*32 + b
    int t = r >> 5, b = r & 31;
    int tok = (t == 0) ? 0 : tgt[b * 41 + (t - 1)];
    tok &= (V_ - 1);                // defensive: never fault on bad data
    const float* src = emb + (size_t)tok * H_;
    for (int h = threadIdx.x; h < H_; h += blockDim.x)
        split_bf(src[h], g_X_hi[(size_t)r * H_ + h], g_X_lo[(size_t)r * H_ + h]);
}

__global__ void k_transpose_enc(const float* __restrict__ enc) {
    int b = blockIdx.x;
    const float* src = enc + (size_t)b * S_ * H_;
    float* dst = g_encT + (size_t)b * H_ * S_;
    for (int i = threadIdx.x; i < S_ * H_; i += blockDim.x) {
        int s = i >> 10, h = i & 1023;
        dst[h * S_ + s] = src[i];
    }
}

// ------------------------- MMA primitive -------------------------
__device__ __forceinline__ void mma16816(float* c, const uint32_t* a, const uint32_t* b) {
    asm volatile(
        "mma.sync.aligned.m16n8k16.row.col.f32.bf16.bf16.f32 "
        "{%0,%1,%2,%3}, {%4,%5,%6,%7}, {%8,%9}, {%0,%1,%2,%3};"
        : "+f"(c[0]), "+f"(c[1]), "+f"(c[2]), "+f"(c[3])
        : "r"(a[0]), "r"(a[1]), "r"(a[2]), "r"(a[3]), "r"(b[0]), "r"(b[1]));
}

// ---------- single-bf16 GEMM: C = A @ B^T (+bias); REMAP: row r=t*32+b -> out row b*T+t ----------
template <int WM, int WN, int NW, bool REMAP>
__global__ void __launch_bounds__(32 * NW)
k_gemm(const bf16* __restrict__ A, int lda,
       const bf16* __restrict__ B, int ldb,
       float* __restrict__ C, int ldc,
       const float* __restrict__ bias,
       int M, int N, int K) {
    const int lane = threadIdx.x & 31, warp = threadIdx.x >> 5;
    const int g = lane >> 2, tg = lane & 3;
    const int m0 = blockIdx.x * (16 * WM);
    const int n0 = blockIdx.y * (8 * WN * NW) + warp * (8 * WN);

    float acc[WM][WN][4];
#pragma unroll
    for (int i = 0; i < WM; i++)
#pragma unroll
        for (int j = 0; j < WN; j++)
#pragma unroll
            for (int q = 0; q < 4; q++) acc[i][j][q] = 0.f;

#pragma unroll 2
    for (int k0 = 0; k0 < K; k0 += 16) {
        uint32_t a[WM][4];
#pragma unroll
        for (int i = 0; i < WM; i++) {
            int r0 = m0 + 16 * i + g;
            int r1 = r0 + 8;
            int ra0 = (r0 < M) ? r0 : (M - 1);
            int ra1 = (r1 < M) ? r1 : (M - 1);
            const uint32_t* p0 = reinterpret_cast<const uint32_t*>(A + (size_t)ra0 * lda + k0);
            const uint32_t* p1 = reinterpret_cast<const uint32_t*>(A + (size_t)ra1 * lda + k0);
            a[i][0] = (r0 < M) ? p0[tg]     : 0u;
            a[i][2] = (r0 < M) ? p0[tg + 4] : 0u;
            a[i][1] = (r1 < M) ? p1[tg]     : 0u;
            a[i][3] = (r1 < M) ? p1[tg + 4] : 0u;
        }
        uint32_t b[WN][2];
#pragma unroll
        for (int j = 0; j < WN; j++) {
            int n = n0 + 8 * j + g;
            const uint32_t* pb = reinterpret_cast<const uint32_t*>(B + (size_t)n * ldb + k0);
            b[j][0] = pb[tg];
            b[j][1] = pb[tg + 4];
        }
#pragma unroll
        for (int i = 0; i < WM; i++)
#pragma unroll
            for (int j = 0; j < WN; j++) mma16816(acc[i][j], a[i], b[j]);
    }

#pragma unroll
    for (int i = 0; i < WM; i++) {
        int r0 = m0 + 16 * i + g;
        int r1 = r0 + 8;
        size_t or0 = REMAP ? ((size_t)(r0 & 31) * T_ + (r0 >> 5)) : (size_t)r0;
        size_t or1 = REMAP ? ((size_t)(r1 & 31) * T_ + (r1 >> 5)) : (size_t)r1;
#pragma unroll
        for (int j = 0; j < WN; j++) {
            int c0 = n0 + 8 * j + 2 * tg;
            float v0 = acc[i][j][0], v1 = acc[i][j][1], v2 = acc[i][j][2], v3 = acc[i][j][3];
            if (bias) {
                float bb0 = bias[c0], bb1 = bias[c0 + 1];
                v0 += bb0; v1 += bb1; v2 += bb0; v3 += bb1;
            }
            if (r0 < M) { C[or0 * ldc + c0] = v0; C[or0 * ldc + c0 + 1] = v1; }
            if (r1 < M) { C[or1 * ldc + c0] = v2; C[or1 * ldc + c0 + 1] = v3; }
        }
    }
}

// --------------- split-bf16 GEMM (~fp32 precision): C = A @ B^T (+bias) ---------------
template <int WM, int WN, int NW>
__global__ void __launch_bounds__(32 * NW)
k_gemm2(const bf16* __restrict__ Ah, const bf16* __restrict__ Al, int lda,
        const bf16* __restrict__ Bh, const bf16* __restrict__ Bl, int ldb,
        float* __restrict__ C, int ldc,
        const float* __restrict__ bias,
        int M, int N, int K) {
    const int lane = threadIdx.x & 31, warp = threadIdx.x >> 5;
    const int g = lane >> 2, tg = lane & 3;
    const int m0 = blockIdx.x * (16 * WM);
    const int n0 = blockIdx.y * (8 * WN * NW) + warp * (8 * WN);

    float acc[WM][WN][4];
#pragma unroll
    for (int i = 0; i < WM; i++)
#pragma unroll
        for (int j = 0; j < WN; j++)
#pragma unroll
            for (int q = 0; q < 4; q++) acc[i][j][q] = 0.f;

#pragma unroll 2
    for (int k0 = 0; k0 < K; k0 += 16) {
        uint32_t ah[WM][4], al[WM][4];
#pragma unroll
        for (int i = 0; i < WM; i++) {
            int r0 = m0 + 16 * i + g;
            int r1 = r0 + 8;
            int ra0 = (r0 < M) ? r0 : (M - 1);
            int ra1 = (r1 < M) ? r1 : (M - 1);
            const uint32_t* ph0 = reinterpret_cast<const uint32_t*>(Ah + (size_t)ra0 * lda + k0);
            const uint32_t* ph1 = reinterpret_cast<const uint32_t*>(Ah + (size_t)ra1 * lda + k0);
            const uint32_t* pl0 = reinterpret_cast<const uint32_t*>(Al + (size_t)ra0 * lda + k0);
            const uint32_t* pl1 = reinterpret_cast<const uint32_t*>(Al + (size_t)ra1 * lda + k0);
            ah[i][0] = (r0 < M) ? ph0[tg]     : 0u;
            ah[i][2] = (r0 < M) ? ph0[tg + 4] : 0u;
            ah[i][1] = (r1 < M) ? ph1[tg]     : 0u;
            ah[i][3] = (r1 < M) ? ph1[tg + 4] : 0u;
            al[i][0] = (r0 < M) ? pl0[tg]     : 0u;
            al[i][2] = (r0 < M) ? pl0[tg + 4] : 0u;
            al[i][1] = (r1 < M) ? pl1[tg]     : 0u;
            al[i][3] = (r1 < M) ? pl1[tg + 4] : 0u;
        }
        uint32_t bh[WN][2], bl[WN][2];
#pragma unroll
        for (int j = 0; j < WN; j++) {
            int n = n0 + 8 * j + g;
            const uint32_t* pbh = reinterpret_cast<const uint32_t*>(Bh + (size_t)n * ldb + k0);
            const uint32_t* pbl = reinterpret_cast<const uint32_t*>(Bl + (size_t)n * ldb + k0);
            bh[j][0] = pbh[tg];
            bh[j][1] = pbh[tg + 4];
            bl[j][0] = pbl[tg];
            bl[j][1] = pbl[tg + 4];
        }
#pragma unroll
        for (int i = 0; i < WM; i++)
#pragma unroll
            for (int j = 0; j < WN; j++) {
                mma16816(acc[i][j], ah[i], bh[j]);
                mma16816(acc[i][j], ah[i], bl[j]);
                mma16816(acc[i][j], al[i], bh[j]);
            }
    }

#pragma unroll
    for (int i = 0; i < WM; i++) {
        int r0 = m0 + 16 * i + g;
        int r1 = r0 + 8;
#pragma unroll
        for (int j = 0; j < WN; j++) {
            int c0 = n0 + 8 * j + 2 * tg;
            float v0 = acc[i][j][0], v1 = acc[i][j][1], v2 = acc[i][j][2], v3 = acc[i][j][3];
            if (bias) {
                float bb0 = bias[c0], bb1 = bias[c0 + 1];
                v0 += bb0; v1 += bb1; v2 += bb0; v3 += bb1;
            }
            if (r0 < M) { C[(size_t)r0 * ldc + c0] = v0; C[(size_t)r0 * ldc + c0 + 1] = v1; }
            if (r1 < M) { C[(size_t)r1 * ldc + c0] = v2; C[(size_t)r1 * ldc + c0 + 1] = v3; }
        }
    }
}

// ============ Phase A: split-K partials of h @ [Wq|Whh]^T  -> g_qA[ks][b][n] ============
// grid (KS_, 80), block 256. Warp covers m=32 (all batches), n=8, K-slice of 256.
__global__ void __launch_bounds__(256) k_qghh() {
    const int tid = threadIdx.x, lane = tid & 31, warp = tid >> 5;
    const int g = lane >> 2, tg = lane & 3;
    const int ks = blockIdx.x;
    const int n0 = (blockIdx.y * 8 + warp) * 8;
    const int kb = ks * KC_;

    float acc[2][4] = {{0.f,0.f,0.f,0.f},{0.f,0.f,0.f,0.f}};
    const bf16* Bh = g_Wqhh_hi + (size_t)(n0 + g) * H_ + kb;
    const bf16* Bl = g_Wqhh_lo + (size_t)(n0 + g) * H_ + kb;

#pragma unroll 8
    for (int k0 = 0; k0 < KC_; k0 += 16) {
        uint32_t bh[2], bl[2];
        const uint32_t* pbh = reinterpret_cast<const uint32_t*>(Bh + k0);
        const uint32_t* pbl = reinterpret_cast<const uint32_t*>(Bl + k0);
        bh[0] = pbh[tg]; bh[1] = pbh[tg + 4];
        bl[0] = pbl[tg]; bl[1] = pbl[tg + 4];
#pragma unroll
        for (int i = 0; i < 2; i++) {
            const int r0 = i * 16 + g, r1 = r0 + 8;
            uint32_t ah[4], al[4];
            const uint32_t* ph0 = reinterpret_cast<const uint32_t*>(g_ctxh_hi + r0 * 2048 + H_ + kb + k0);
            const uint32_t* ph1 = reinterpret_cast<const uint32_t*>(g_ctxh_hi + r1 * 2048 + H_ + kb + k0);
            const uint32_t* pl0 = reinterpret_cast<const uint32_t*>(g_ctxh_lo + r0 * 2048 + H_ + kb + k0);
            const uint32_t* pl1 = reinterpret_cast<const uint32_t*>(g_ctxh_lo + r1 * 2048 + H_ + kb + k0);
            ah[0] = ph0[tg]; ah[2] = ph0[tg + 4];
            ah[1] = ph1[tg]; ah[3] = ph1[tg + 4];
            al[0] = pl0[tg]; al[2] = pl0[tg + 4];
            al[1] = pl1[tg]; al[3] = pl1[tg + 4];
            mma16816(acc[i], ah, bh);
            mma16816(acc[i], ah, bl);
            mma16816(acc[i], al, bh);
        }
    }

    const int c0 = n0 + 2 * tg;
    float* dst = g_qA + (size_t)ks * B_ * NA_;
#pragma unroll
    for (int i = 0; i < 2; i++) {
        const int r0 = i * 16 + g, r1 = r0 + 8;
        dst[r0 * NA_ + c0]     = acc[i][0];
        dst[r0 * NA_ + c0 + 1] = acc[i][1];
        dst[r1 * NA_ + c0]     = acc[i][2];
        dst[r1 * NA_ + c0 + 1] = acc[i][3];
    }
}

// ------------------------- Phase B: attention (scores, softmax, ctx) -------------------------
__global__ void __launch_bounds__(256) k_attn(const float* __restrict__ Vw,
                                              const float* __restrict__ bV,
                                              const float* __restrict__ bq,
                                              float* __restrict__ out_attn, int t) {
    __shared__ float sq[H_], sv[H_], ssc[48];
    const int b = blockIdx.x, tid = threadIdx.x;
    const int warp = tid >> 5, lane = tid & 31;

    for (int i = tid; i < H_; i += 256) {
        float q = bq[i];
#pragma unroll
        for (int s = 0; s < KS_; s++) q += g_qA[(size_t)s * B_ * NA_ + b * NA_ + i];
        sq[i] = q;
        sv[i] = Vw[i];
    }
    __syncthreads();

    for (int s = warp; s < S_; s += 8) {
        const float* kp = g_keys + ((size_t)b * S_ + s) * H_;
        float a = 0.f;
        for (int h = lane; h < H_; h += 32)
            a += tanhf(sq[h] + kp[h]) * sv[h];
#pragma unroll
        for (int o = 16; o; o >>= 1) a += __shfl_xor_sync(0xffffffffu, a, o);
        if (lane == 0) ssc[s] = a + bV[0];
    }
    __syncthreads();

    if (warp == 0) {
        float v0 = ssc[lane];
        float v1 = (lane < S_ - 32) ? ssc[lane + 32] : -INFINITY;
        float m = fmaxf(v0, v1);
#pragma unroll
        for (int o = 16; o; o >>= 1) m = fmaxf(m, __shfl_xor_sync(0xffffffffu, m, o));
        float e0 = expf(v0 - m);
        float e1 = (lane < S_ - 32) ? expf(v1 - m) : 0.f;
        float s = e0 + e1;
#pragma unroll
        for (int o = 16; o; o >>= 1) s += __shfl_xor_sync(0xffffffffu, s, o);
        float inv = 1.f / s;
        float w0 = e0 * inv;
        ssc[lane] = w0;
        out_attn[((size_t)b * T_ + t) * S_ + lane] = w0;
        if (lane < S_ - 32) {
            float w1 = e1 * inv;
            ssc[lane + 32] = w1;
            out_attn[((size_t)b * T_ + t) * S_ + lane + 32] = w1;
        }
    }
    __syncthreads();

    for (int h = tid; h < H_; h += 256) {
        const float* ep = g_encT + ((size_t)b * H_ + h) * S_;
        float a = 0.f;
#pragma unroll
        for (int s = 0; s < S_; s++) a += ssc[s] * ep[s];
        split_bf(a, g_ctxh_hi[b * 2048 + h], g_ctxh_lo[b * 2048 + h]);
    }
}

// ============ Phase C: split-K partials of ctx @ Wc^T -> g_gp[ks][b][col] ============
// grid (KS_, 128), block 256. Per block: 8 cols across 4 gate quadrants, m=32, K-slice 256.
__global__ void __launch_bounds__(256) k_gatesmm() {
    const int tid = threadIdx.x, lane = tid & 31, warp = tid >> 5;
    const int g = lane >> 2, tg = lane & 3;
    const int ks = blockIdx.x;
    const int j0 = blockIdx.y * 8;
    const int qg = warp >> 1, mh = warp & 1;
    const int m0 = mh * 16;
    const int ng = qg * 1024 + j0;
    const int kb = ks * KC_;

    float acc[4] = {0.f, 0.f, 0.f, 0.f};
    const int r0 = m0 + g, r1 = r0 + 8;
    const bf16* Ah0 = g_ctxh_hi + r0 * 2048 + kb;
    const bf16* Ah1 = g_ctxh_hi + r1 * 2048 + kb;
    const bf16* Al0 = g_ctxh_lo + r0 * 2048 + kb;
    const bf16* Al1 = g_ctxh_lo + r1 * 2048 + kb;
    const bf16* Bh = g_Wc_hi + (size_t)(ng + g) * H_ + kb;
    const bf16* Bl = g_Wc_lo + (size_t)(ng + g) * H_ + kb;

#pragma unroll 8
    for (int k0 = 0; k0 < KC_; k0 += 16) {
        uint32_t ah[4], al[4], bh[2], bl[2];
        const uint32_t* ph0 = reinterpret_cast<const uint32_t*>(Ah0 + k0);
        const uint32_t* ph1 = reinterpret_cast<const uint32_t*>(Ah1 + k0);
        const uint32_t* pl0 = reinterpret_cast<const uint32_t*>(Al0 + k0);
        const uint32_t* pl1 = reinterpret_cast<const uint32_t*>(Al1 + k0);
        const uint32_t* pbh = reinterpret_cast<const uint32_t*>(Bh + k0);
        const uint32_t* pbl = reinterpret_cast<const uint32_t*>(Bl + k0);
        ah[0] = ph0[tg]; ah[2] = ph0[tg + 4];
        ah[1] = ph1[tg]; ah[3] = ph1[tg + 4];
        al[0] = pl0[tg]; al[2] = pl0[tg + 4];
        al[1] = pl1[tg]; al[3] = pl1[tg + 4];
        bh[0] = pbh[tg]; bh[1] = pbh[tg + 4];
        bl[0] = pbl[tg]; bl[1] = pbl[tg + 4];
        mma16816(acc, ah, bh);
        mma16816(acc, ah, bl);
        mma16816(acc, al, bh);
    }

    float* dst = g_gp + (size_t)ks * B_ * G_;
    const int c0 = ng + 2 * tg;
    dst[(size_t)r0 * G_ + c0]     = acc[0];
    dst[(size_t)r0 * G_ + c0 + 1] = acc[1];
    dst[(size_t)r1 * G_ + c0]     = acc[2];
    dst[(size_t)r1 * G_ + c0 + 1] = acc[3];
}

// ---------------- Phase C2: sum partials + gpre + ghh, LSTM update ----------------
// grid 128, block 256: thread (b, jj) handles column j = blockIdx.x*8 + jj for all 4 gates.
__global__ void __launch_bounds__(256) k_update2(int t) {
    const int tid = threadIdx.x;
    const int b = tid >> 3, jj = tid & 7;
    const int j = blockIdx.x * 8 + jj;
    const float* gpre = g_gates_pre + (size_t)t * B_ * G_ + (size_t)b * G_;

    float gate[4];
#pragma unroll
    for (int qc = 0; qc < 4; qc++) {
        int col = qc * 1024 + j;
        float v = gpre[col];
#pragma unroll
        for (int s = 0; s < KS_; s++) {
            v += g_gp[(size_t)s * B_ * G_ + (size_t)b * G_ + col];
            v += g_qA[(size_t)s * B_ * NA_ + b * NA_ + H_ + col];
        }
        gate[qc] = v;
    }

    float ig = 1.f / (1.f + expf(-gate[0]));
    float fg = 1.f / (1.f + expf(-gate[1]));
    float gg = tanhf(gate[2]);
    float og = 1.f / (1.f + expf(-gate[3]));
    int par = t & 1;
    int idx = b * H_ + j;
    float c = fg * g_c[par][idx] + ig * gg;
    float h = og * tanhf(c);
    g_c[par ^ 1][idx] = c;
    g_h[par ^ 1][idx] = h;
    split_bf(h, g_ctxh_hi[b * 2048 + H_ + j], g_ctxh_lo[b * 2048 + H_ + j]);
    g_Hbf[(size_t)(t * B_ + b) * H_ + j] = __float2bfloat16(h);
}

// ------------------------- in-place log-softmax over V per output row -------------------------
__global__ void __launch_bounds__(256) k_logsoftmax(float* __restrict__ out) {
    __shared__ float red[8];
    __shared__ float bc;
    const int r = blockIdx.x;
    float* x = out + OUT_DEC + (size_t)r * V_;
    const int tid = threadIdx.x, lane = tid & 31, warp = tid >> 5;

    float m = -INFINITY;
    for (int v = tid; v < V_; v += 256) m = fmaxf(m, x[v]);
#pragma unroll
    for (int o2 = 16; o2; o2 >>= 1) m = fmaxf(m, __shfl_xor_sync(0xffffffffu, m, o2));
    if (lane == 0) red[warp] = m;
    __syncthreads();
    if (tid == 0) {
        float mm = red[0];
#pragma unroll
        for (int w = 1; w < 8; w++) mm = fmaxf(mm, red[w]);
        bc = mm;
    }
    __syncthreads();
    m = bc;

    float s = 0.f;
    for (int v = tid; v < V_; v += 256) s += expf(x[v] - m);
#pragma unroll
    for (int o2 = 16; o2; o2 >>= 1) s += __shfl_xor_sync(0xffffffffu, s, o2);
    __syncthreads();
    if (lane == 0) red[warp] = s;
    __syncthreads();
    if (tid == 0) {
        float ss = 0.f;
#pragma unroll
        for (int w = 0; w < 8; w++) ss += red[w];
        bc = m + logf(ss);
    }
    __syncthreads();
    float ls = bc;

    for (int v = tid; v < V_; v += 256) x[v] -= ls;
}

// ------------------------- final state copy -------------------------
__global__ void __launch_bounds__(256) k_final(float* __restrict__ out) {
    int i = blockIdx.x * blockDim.x + threadIdx.x;
    if (i < B_ * H_) {
        out[OUT_HF + i] = g_h[1][i];
        out[OUT_CF + i] = g_c[1][i];
    }
}

// ------------------------- launch -------------------------
extern "C" void kernel_launch(void* const* d_in, const int* in_sizes, int n_in,
                              void* d_out, int out_size) {
    (void)in_sizes; (void)n_in; (void)out_size;
    const float* enc  = (const float*)d_in[0];
    const float* ehid = (const float*)d_in[1];
    const int*   tgt  = (const int*)d_in[2];
    const float* emb  = (const float*)d_in[3];
    const float* Wq   = (const float*)d_in[4];
    const float* bq   = (const float*)d_in[5];
    const float* Wk   = (const float*)d_in[6];
    const float* bk   = (const float*)d_in[7];
    const float* Vw   = (const float*)d_in[8];
    const float* bV   = (const float*)d_in[9];
    const float* Wih  = (const float*)d_in[10];
    const float* Whh  = (const float*)d_in[11];
    const float* bih  = (const float*)d_in[12];
    const float* bhh  = (const float*)d_in[13];
    const float* Wout = (const float*)d_in[14];
    const float* bout = (const float*)d_in[15];
    float* out = (float*)d_out;

    void *p_enc_hi, *p_enc_lo, *p_Wk_hi, *p_Wk_lo, *p_Wx_hi, *p_Wx_lo,
         *p_Wout, *p_X_hi, *p_X_lo, *p_keys, *p_gpre, *p_Hbf, *p_bsum;
    cudaGetSymbolAddress(&p_enc_hi, g_enc_hi);
    cudaGetSymbolAddress(&p_enc_lo, g_enc_lo);
    cudaGetSymbolAddress(&p_Wk_hi, g_Wk_hi);
    cudaGetSymbolAddress(&p_Wk_lo, g_Wk_lo);
    cudaGetSymbolAddress(&p_Wx_hi, g_Wx_hi);
    cudaGetSymbolAddress(&p_Wx_lo, g_Wx_lo);
    cudaGetSymbolAddress(&p_Wout, g_Wout_bf);
    cudaGetSymbolAddress(&p_X_hi, g_X_hi);
    cudaGetSymbolAddress(&p_X_lo, g_X_lo);
    cudaGetSymbolAddress(&p_keys, g_keys);
    cudaGetSymbolAddress(&p_gpre, g_gates_pre);
    cudaGetSymbolAddress(&p_Hbf, g_Hbf);
    cudaGetSymbolAddress(&p_bsum, g_bsum);

    // prep
    k_cvt2<<<2048, 256>>>(enc, (bf16*)p_enc_hi, (bf16*)p_enc_lo, TB_ * H_);
    k_transpose_enc<<<B_, 256>>>(enc);
    k_cvt2<<<1024, 256>>>(Wk, (bf16*)p_Wk_hi, (bf16*)p_Wk_lo, H_ * H_);
    k_cvt<<<4096, 256>>>(Wout, (bf16*)p_Wout, V_ * H_);
    k_wqhh<<<4096, 256>>>(Wq, Whh);
    k_cvt_wx<<<4096, 256>>>(Wih);
    k_wc<<<4096, 256>>>(Wih);
    k_bias<<<16, 256>>>(bih, bhh);
    k_init<<<128, 256>>>(ehid);
    k_gather<<<TB_, 256>>>(emb, tgt);

    // hoisted GEMMs (split precision)
    {   // keys_proj = enc @ Wk^T + bk : [1312,1024]
        dim3 grid((TB_ + 63) / 64, H_ / 128);
        k_gemm2<4, 2, 8><<<grid, 256>>>((const bf16*)p_enc_hi, (const bf16*)p_enc_lo, H_,
                                        (const bf16*)p_Wk_hi, (const bf16*)p_Wk_lo, H_,
                                        (float*)p_keys, H_, bk, TB_, H_, H_);
    }
    {   // gates_pre = X @ Wx^T + (bih+bhh) : [1312,4096]
        dim3 grid((TB_ + 63) / 64, G_ / 128);
        k_gemm2<4, 2, 8><<<grid, 256>>>((const bf16*)p_X_hi, (const bf16*)p_X_lo, H_,
                                        (const bf16*)p_Wx_hi, (const bf16*)p_Wx_lo, H_,
                                        (float*)p_gpre, G_, (const float*)p_bsum, TB_, G_, H_);
    }

    // sequential decode: 4 launches per step, all phases chip-wide via split-K
    for (int t = 0; t < T_; t++) {
        k_qghh<<<dim3(KS_, 80), 256>>>();
        k_attn<<<B_, 256>>>(Vw, bV, bq, out + OUT_ATTN, t);
        k_gatesmm<<<dim3(KS_, 128), 256>>>();
        k_update2<<<128, 256>>>(t);
    }

    {   // logits -> directly into out[OUT_DEC] at [b,t,:] via remap epilogue
        dim3 grid((TB_ + 63) / 64, V_ / 128);
        k_gemm<4, 2, 8, true><<<grid, 256>>>((const bf16*)p_Hbf, H_, (const bf16*)p_Wout, H_,
                                             out + OUT_DEC, V_, bout, TB_, V_, H_);
    }
    k_logsoftmax<<<TB_, 256>>>(out);
    k_final<<<128, 256>>>(out);
}

// round 10
// speedup vs baseline: 1.1565x; 1.0751x over previous
#include <cuda_runtime.h>
#include <cuda_bf16.h>
#include <cstdint>

using bf16 = __nv_bfloat16;

#define B_  32
#define S_  41
#define T_  41
#define H_  1024
#define V_  16384
#define G_  4096
#define NA_ 5120   // combined q(1024) + ghh(4096)
#define TB_ 1312   // T_*B_
#define KS_ 4      // split-K factor for loop GEMMs
#define KC_ (H_ / KS_)   // 256

// output layout (flattened concat of reference return values, fp32)
#define OUT_DEC  0ull
#define OUT_HF   21495808ull
#define OUT_CF   21528576ull
#define OUT_ATTN 21561344ull

// ------------------------- device scratch (static, no allocs) -------------------------
__device__ bf16  g_enc_hi[TB_ * H_];
__device__ bf16  g_enc_lo[TB_ * H_];
__device__ float g_encT[B_ * H_ * S_];          // enc transposed [b,h,s]
__device__ bf16  g_Wk_hi[H_ * H_];
__device__ bf16  g_Wk_lo[H_ * H_];
__device__ bf16  g_Wqhh_hi[NA_ * H_];           // rows 0..1023 = Wq; 1024..5119 = Whh
__device__ bf16  g_Wqhh_lo[NA_ * H_];
__device__ bf16  g_Wx_hi[G_ * H_];              // Wih[:, 0:1024]   (x part)
__device__ bf16  g_Wx_lo[G_ * H_];
__device__ bf16  g_Wc_hi[G_ * H_];              // Wih[:, 1024:2048] (ctx part)
__device__ bf16  g_Wc_lo[G_ * H_];
__device__ bf16  g_Wout_bf[(size_t)V_ * H_];
__device__ bf16  g_X_hi[TB_ * H_];
__device__ bf16  g_X_lo[TB_ * H_];
__device__ float g_keys[TB_ * H_];
__device__ float g_gates_pre[(size_t)TB_ * G_]; // X@Wx^T + bih + bhh
__device__ float g_qA[KS_ * B_ * NA_];          // split-K partials of h@[Wq|Whh]^T
__device__ float g_gp[KS_ * B_ * G_];           // split-K partials of ctx@Wc^T
__device__ float g_scores[B_ * S_];             // attention scores per step
__device__ bf16  g_ctxh_hi[B_ * 2 * H_];        // per b: [ctx(1024) | h(1024)]
__device__ bf16  g_ctxh_lo[B_ * 2 * H_];
__device__ float g_h[2][B_ * H_];
__device__ float g_c[2][B_ * H_];
__device__ bf16  g_Hbf[TB_ * H_];
__device__ float g_bsum[G_];

__device__ __forceinline__ void split_bf(float v, bf16& hi, bf16& lo) {
    bf16 h = __float2bfloat16(v);
    hi = h;
    lo = __float2bfloat16(v - __bfloat162float(h));
}

// ------------------------- ONE merged prep kernel (grid-stride segments) -------------------------
__global__ void k_prep(const float* __restrict__ enc, const float* __restrict__ ehid,
                       const float* __restrict__ Wq, const float* __restrict__ Wk,
                       const float* __restrict__ Wih, const float* __restrict__ Whh,
                       const float* __restrict__ bih, const float* __restrict__ bhh,
                       const float* __restrict__ Wout) {
    const int stride = gridDim.x * blockDim.x;
    const int tid0 = blockIdx.x * blockDim.x + threadIdx.x;

    // enc -> hi/lo bf16
    for (int i = tid0; i < TB_ * H_; i += stride)
        split_bf(enc[i], g_enc_hi[i], g_enc_lo[i]);
    // enc -> transposed fp32 [b,h,s]
    for (int i = tid0; i < B_ * S_ * H_; i += stride) {
        int b = i >> 10 ; int h = i & 1023; int bs = b; // i = (b*S_+s)*H_... recompute:
        int row = i >> 10;          // b*S_+s
        int s = row % S_;
        int bb = row / S_;
        g_encT[((size_t)bb * H_ + h) * S_ + s] = enc[i];
        (void)bs;
    }
    // Wk -> hi/lo
    for (int i = tid0; i < H_ * H_; i += stride)
        split_bf(Wk[i], g_Wk_hi[i], g_Wk_lo[i]);
    // Wout -> bf16
    for (size_t i = tid0; i < (size_t)V_ * H_; i += stride)
        g_Wout_bf[i] = __float2bfloat16(Wout[i]);
    // [Wq|Whh] -> hi/lo
    for (int i = tid0; i < NA_ * H_; i += stride) {
        int n = i >> 10, k = i & 1023;
        float v = (n < 1024) ? Wq[(size_t)n * H_ + k] : Whh[(size_t)(n - 1024) * H_ + k];
        split_bf(v, g_Wqhh_hi[i], g_Wqhh_lo[i]);
    }
    // Wih x-part -> hi/lo
    for (int i = tid0; i < G_ * H_; i += stride) {
        int n = i >> 10, k = i & 1023;
        split_bf(Wih[(size_t)n * 2048 + k], g_Wx_hi[i], g_Wx_lo[i]);
    }
    // Wih ctx-part -> hi/lo
    for (int i = tid0; i < G_ * H_; i += stride) {
        int n = i >> 10, k = i & 1023;
        split_bf(Wih[(size_t)n * 2048 + 1024 + k], g_Wc_hi[i], g_Wc_lo[i]);
    }
    // bias sum
    for (int i = tid0; i < G_; i += stride)
        g_bsum[i] = bih[i] + bhh[i];
    // init h/c state
    for (int i = tid0; i < B_ * H_; i += stride) {
        float h = ehid[i];
        g_c[0][i] = 0.f;
        g_h[0][i] = h;
        int b = i >> 10, j = i & 1023;
        split_bf(h, g_ctxh_hi[b * 2048 + 1024 + j], g_ctxh_lo[b * 2048 + 1024 + j]);
    }
}

// NOTE: target_tensor is int32 on the wire (JAX downcasts int64 without x64 mode).
__global__ void k_gather(const float* __restrict__ emb, const int* __restrict__ tgt) {
    int r = blockIdx.x;             // r = t*32 + b
    int t = r >> 5, b = r & 31;
    int tok = (t == 0) ? 0 : tgt[b * 41 + (t - 1)];
    tok &= (V_ - 1);                // defensive: never fault on bad data
    const float* src = emb + (size_t)tok * H_;
    for (int h = threadIdx.x; h < H_; h += blockDim.x)
        split_bf(src[h], g_X_hi[(size_t)r * H_ + h], g_X_lo[(size_t)r * H_ + h]);
}

// ------------------------- MMA primitive -------------------------
__device__ __forceinline__ void mma16816(float* c, const uint32_t* a, const uint32_t* b) {
    asm volatile(
        "mma.sync.aligned.m16n8k16.row.col.f32.bf16.bf16.f32 "
        "{%0,%1,%2,%3}, {%4,%5,%6,%7}, {%8,%9}, {%0,%1,%2,%3};"
        : "+f"(c[0]), "+f"(c[1]), "+f"(c[2]), "+f"(c[3])
        : "r"(a[0]), "r"(a[1]), "r"(a[2]), "r"(a[3]), "r"(b[0]), "r"(b[1]));
}

// ---------- single-bf16 GEMM: C = A @ B^T (+bias); REMAP: row r=t*32+b -> out row b*T+t ----------
template <int WM, int WN, int NW, bool REMAP>
__global__ void __launch_bounds__(32 * NW)
k_gemm(const bf16* __restrict__ A, int lda,
       const bf16* __restrict__ B, int ldb,
       float* __restrict__ C, int ldc,
       const float* __restrict__ bias,
       int M, int N, int K) {
    const int lane = threadIdx.x & 31, warp = threadIdx.x >> 5;
    const int g = lane >> 2, tg = lane & 3;
    const int m0 = blockIdx.x * (16 * WM);
    const int n0 = blockIdx.y * (8 * WN * NW) + warp * (8 * WN);

    float acc[WM][WN][4];
#pragma unroll
    for (int i = 0; i < WM; i++)
#pragma unroll
        for (int j = 0; j < WN; j++)
#pragma unroll
            for (int q = 0; q < 4; q++) acc[i][j][q] = 0.f;

#pragma unroll 2
    for (int k0 = 0; k0 < K; k0 += 16) {
        uint32_t a[WM][4];
#pragma unroll
        for (int i = 0; i < WM; i++) {
            int r0 = m0 + 16 * i + g;
            int r1 = r0 + 8;
            int ra0 = (r0 < M) ? r0 : (M - 1);
            int ra1 = (r1 < M) ? r1 : (M - 1);
            const uint32_t* p0 = reinterpret_cast<const uint32_t*>(A + (size_t)ra0 * lda + k0);
            const uint32_t* p1 = reinterpret_cast<const uint32_t*>(A + (size_t)ra1 * lda + k0);
            a[i][0] = (r0 < M) ? p0[tg]     : 0u;
            a[i][2] = (r0 < M) ? p0[tg + 4] : 0u;
            a[i][1] = (r1 < M) ? p1[tg]     : 0u;
            a[i][3] = (r1 < M) ? p1[tg + 4] : 0u;
        }
        uint32_t b[WN][2];
#pragma unroll
        for (int j = 0; j < WN; j++) {
            int n = n0 + 8 * j + g;
            const uint32_t* pb = reinterpret_cast<const uint32_t*>(B + (size_t)n * ldb + k0);
            b[j][0] = pb[tg];
            b[j][1] = pb[tg + 4];
        }
#pragma unroll
        for (int i = 0; i < WM; i++)
#pragma unroll
            for (int j = 0; j < WN; j++) mma16816(acc[i][j], a[i], b[j]);
    }

#pragma unroll
    for (int i = 0; i < WM; i++) {
        int r0 = m0 + 16 * i + g;
        int r1 = r0 + 8;
        size_t or0 = REMAP ? ((size_t)(r0 & 31) * T_ + (r0 >> 5)) : (size_t)r0;
        size_t or1 = REMAP ? ((size_t)(r1 & 31) * T_ + (r1 >> 5)) : (size_t)r1;
#pragma unroll
        for (int j = 0; j < WN; j++) {
            int c0 = n0 + 8 * j + 2 * tg;
            float v0 = acc[i][j][0], v1 = acc[i][j][1], v2 = acc[i][j][2], v3 = acc[i][j][3];
            if (bias) {
                float bb0 = bias[c0], bb1 = bias[c0 + 1];
                v0 += bb0; v1 += bb1; v2 += bb0; v3 += bb1;
            }
            if (r0 < M) { C[or0 * ldc + c0] = v0; C[or0 * ldc + c0 + 1] = v1; }
            if (r1 < M) { C[or1 * ldc + c0] = v2; C[or1 * ldc + c0 + 1] = v3; }
        }
    }
}

// --------------- split-bf16 GEMM (~fp32 precision): C = A @ B^T (+bias) ---------------
template <int WM, int WN, int NW>
__global__ void __launch_bounds__(32 * NW)
k_gemm2(const bf16* __restrict__ Ah, const bf16* __restrict__ Al, int lda,
        const bf16* __restrict__ Bh, const bf16* __restrict__ Bl, int ldb,
        float* __restrict__ C, int ldc,
        const float* __restrict__ bias,
        int M, int N, int K) {
    const int lane = threadIdx.x & 31, warp = threadIdx.x >> 5;
    const int g = lane >> 2, tg = lane & 3;
    const int m0 = blockIdx.x * (16 * WM);
    const int n0 = blockIdx.y * (8 * WN * NW) + warp * (8 * WN);

    float acc[WM][WN][4];
#pragma unroll
    for (int i = 0; i < WM; i++)
#pragma unroll
        for (int j = 0; j < WN; j++)
#pragma unroll
            for (int q = 0; q < 4; q++) acc[i][j][q] = 0.f;

#pragma unroll 2
    for (int k0 = 0; k0 < K; k0 += 16) {
        uint32_t ah[WM][4], al[WM][4];
#pragma unroll
        for (int i = 0; i < WM; i++) {
            int r0 = m0 + 16 * i + g;
            int r1 = r0 + 8;
            int ra0 = (r0 < M) ? r0 : (M - 1);
            int ra1 = (r1 < M) ? r1 : (M - 1);
            const uint32_t* ph0 = reinterpret_cast<const uint32_t*>(Ah + (size_t)ra0 * lda + k0);
            const uint32_t* ph1 = reinterpret_cast<const uint32_t*>(Ah + (size_t)ra1 * lda + k0);
            const uint32_t* pl0 = reinterpret_cast<const uint32_t*>(Al + (size_t)ra0 * lda + k0);
            const uint32_t* pl1 = reinterpret_cast<const uint32_t*>(Al + (size_t)ra1 * lda + k0);
            ah[i][0] = (r0 < M) ? ph0[tg]     : 0u;
            ah[i][2] = (r0 < M) ? ph0[tg + 4] : 0u;
            ah[i][1] = (r1 < M) ? ph1[tg]     : 0u;
            ah[i][3] = (r1 < M) ? ph1[tg + 4] : 0u;
            al[i][0] = (r0 < M) ? pl0[tg]     : 0u;
            al[i][2] = (r0 < M) ? pl0[tg + 4] : 0u;
            al[i][1] = (r1 < M) ? pl1[tg]     : 0u;
            al[i][3] = (r1 < M) ? pl1[tg + 4] : 0u;
        }
        uint32_t bh[WN][2], bl[WN][2];
#pragma unroll
        for (int j = 0; j < WN; j++) {
            int n = n0 + 8 * j + g;
            const uint32_t* pbh = reinterpret_cast<const uint32_t*>(Bh + (size_t)n * ldb + k0);
            const uint32_t* pbl = reinterpret_cast<const uint32_t*>(Bl + (size_t)n * ldb + k0);
            bh[j][0] = pbh[tg];
            bh[j][1] = pbh[tg + 4];
            bl[j][0] = pbl[tg];
            bl[j][1] = pbl[tg + 4];
        }
#pragma unroll
        for (int i = 0; i < WM; i++)
#pragma unroll
            for (int j = 0; j < WN; j++) {
                mma16816(acc[i][j], ah[i], bh[j]);
                mma16816(acc[i][j], ah[i], bl[j]);
                mma16816(acc[i][j], al[i], bh[j]);
            }
    }

#pragma unroll
    for (int i = 0; i < WM; i++) {
        int r0 = m0 + 16 * i + g;
        int r1 = r0 + 8;
#pragma unroll
        for (int j = 0; j < WN; j++) {
            int c0 = n0 + 8 * j + 2 * tg;
            float v0 = acc[i][j][0], v1 = acc[i][j][1], v2 = acc[i][j][2], v3 = acc[i][j][3];
            if (bias) {
                float bb0 = bias[c0], bb1 = bias[c0 + 1];
                v0 += bb0; v1 += bb1; v2 += bb0; v3 += bb1;
            }
            if (r0 < M) { C[(size_t)r0 * ldc + c0] = v0; C[(size_t)r0 * ldc + c0 + 1] = v1; }
            if (r1 < M) { C[(size_t)r1 * ldc + c0] = v2; C[(size_t)r1 * ldc + c0 + 1] = v3; }
        }
    }
}

// ============ Phase A: split-K partials of h @ [Wq|Whh]^T  -> g_qA[ks][b][n] ============
__global__ void __launch_bounds__(256) k_qghh() {
    const int tid = threadIdx.x, lane = tid & 31, warp = tid >> 5;
    const int g = lane >> 2, tg = lane & 3;
    const int ks = blockIdx.x;
    const int n0 = (blockIdx.y * 8 + warp) * 8;
    const int kb = ks * KC_;

    float acc[2][4] = {{0.f,0.f,0.f,0.f},{0.f,0.f,0.f,0.f}};
    const bf16* Bh = g_Wqhh_hi + (size_t)(n0 + g) * H_ + kb;
    const bf16* Bl = g_Wqhh_lo + (size_t)(n0 + g) * H_ + kb;

#pragma unroll 8
    for (int k0 = 0; k0 < KC_; k0 += 16) {
        uint32_t bh[2], bl[2];
        const uint32_t* pbh = reinterpret_cast<const uint32_t*>(Bh + k0);
        const uint32_t* pbl = reinterpret_cast<const uint32_t*>(Bl + k0);
        bh[0] = pbh[tg]; bh[1] = pbh[tg + 4];
        bl[0] = pbl[tg]; bl[1] = pbl[tg + 4];
#pragma unroll
        for (int i = 0; i < 2; i++) {
            const int r0 = i * 16 + g, r1 = r0 + 8;
            uint32_t ah[4], al[4];
            const uint32_t* ph0 = reinterpret_cast<const uint32_t*>(g_ctxh_hi + r0 * 2048 + H_ + kb + k0);
            const uint32_t* ph1 = reinterpret_cast<const uint32_t*>(g_ctxh_hi + r1 * 2048 + H_ + kb + k0);
            const uint32_t* pl0 = reinterpret_cast<const uint32_t*>(g_ctxh_lo + r0 * 2048 + H_ + kb + k0);
            const uint32_t* pl1 = reinterpret_cast<const uint32_t*>(g_ctxh_lo + r1 * 2048 + H_ + kb + k0);
            ah[0] = ph0[tg]; ah[2] = ph0[tg + 4];
            ah[1] = ph1[tg]; ah[3] = ph1[tg + 4];
            al[0] = pl0[tg]; al[2] = pl0[tg + 4];
            al[1] = pl1[tg]; al[3] = pl1[tg + 4];
            mma16816(acc[i], ah, bh);
            mma16816(acc[i], ah, bl);
            mma16816(acc[i], al, bh);
        }
    }

    const int c0 = n0 + 2 * tg;
    float* dst = g_qA + (size_t)ks * B_ * NA_;
#pragma unroll
    for (int i = 0; i < 2; i++) {
        const int r0 = i * 16 + g, r1 = r0 + 8;
        dst[r0 * NA_ + c0]     = acc[i][0];
        dst[r0 * NA_ + c0 + 1] = acc[i][1];
        dst[r1 * NA_ + c0]     = acc[i][2];
        dst[r1 * NA_ + c0 + 1] = acc[i][3];
    }
}

// ============ Phase B1: scores — one block per (s,b), chip-wide MUFU spread ============
__global__ void __launch_bounds__(128) k_scores(const float* __restrict__ Vw,
                                                const float* __restrict__ bq,
                                                const float* __restrict__ bV) {
    const int s = blockIdx.x, b = blockIdx.y;
    const int tid = threadIdx.x, lane = tid & 31, warp = tid >> 5;
    __shared__ float red[4];

    const float* kp = g_keys + ((size_t)b * S_ + s) * H_;
    float a = 0.f;
    for (int h = tid; h < H_; h += 128) {
        float q = bq[h];
#pragma unroll
        for (int ks = 0; ks < KS_; ks++) q += g_qA[(size_t)ks * B_ * NA_ + b * NA_ + h];
        a += tanhf(q + kp[h]) * Vw[h];
    }
#pragma unroll
    for (int o = 16; o; o >>= 1) a += __shfl_xor_sync(0xffffffffu, a, o);
    if (lane == 0) red[warp] = a;
    __syncthreads();
    if (tid == 0)
        g_scores[b * S_ + s] = red[0] + red[1] + red[2] + red[3] + bV[0];
}

// ============ Phase B2: softmax + attn output + ctx (32 blocks) ============
__global__ void __launch_bounds__(256) k_softctx(float* __restrict__ out_attn, int t) {
    __shared__ float ssc[48];
    const int b = blockIdx.x, tid = threadIdx.x;
    const int warp = tid >> 5, lane = tid & 31;

    if (warp == 0) {
        float v0 = g_scores[b * S_ + ((lane < S_) ? lane : 0)];
        if (lane >= S_) v0 = -INFINITY;
        float v1 = (lane < S_ - 32) ? g_scores[b * S_ + lane + 32] : -INFINITY;
        float m = fmaxf(v0, v1);
#pragma unroll
        for (int o = 16; o; o >>= 1) m = fmaxf(m, __shfl_xor_sync(0xffffffffu, m, o));
        float e0 = (lane < S_) ? expf(v0 - m) : 0.f;
        float e1 = (lane < S_ - 32) ? expf(v1 - m) : 0.f;
        float s = e0 + e1;
#pragma unroll
        for (int o = 16; o; o >>= 1) s += __shfl_xor_sync(0xffffffffu, s, o);
        float inv = 1.f / s;
        if (lane < S_) {
            float w0 = e0 * inv;
            ssc[lane] = w0;
            out_attn[((size_t)b * T_ + t) * S_ + lane] = w0;
        }
        if (lane < S_ - 32) {
            float w1 = e1 * inv;
            ssc[lane + 32] = w1;
            out_attn[((size_t)b * T_ + t) * S_ + lane + 32] = w1;
        }
    }
    __syncthreads();

    for (int h = tid; h < H_; h += 256) {
        const float* ep = g_encT + ((size_t)b * H_ + h) * S_;
        float a = 0.f;
#pragma unroll
        for (int s = 0; s < S_; s++) a += ssc[s] * ep[s];
        split_bf(a, g_ctxh_hi[b * 2048 + h], g_ctxh_lo[b * 2048 + h]);
    }
}

// ============ Phase C: split-K partials of ctx @ Wc^T -> g_gp[ks][b][col] ============
__global__ void __launch_bounds__(256) k_gatesmm() {
    const int tid = threadIdx.x, lane = tid & 31, warp = tid >> 5;
    const int g = lane >> 2, tg = lane & 3;
    const int ks = blockIdx.x;
    const int j0 = blockIdx.y * 8;
    const int qg = warp >> 1, mh = warp & 1;
    const int m0 = mh * 16;
    const int ng = qg * 1024 + j0;
    const int kb = ks * KC_;

    float acc[4] = {0.f, 0.f, 0.f, 0.f};
    const int r0 = m0 + g, r1 = r0 + 8;
    const bf16* Ah0 = g_ctxh_hi + r0 * 2048 + kb;
    const bf16* Ah1 = g_ctxh_hi + r1 * 2048 + kb;
    const bf16* Al0 = g_ctxh_lo + r0 * 2048 + kb;
    const bf16* Al1 = g_ctxh_lo + r1 * 2048 + kb;
    const bf16* Bh = g_Wc_hi + (size_t)(ng + g) * H_ + kb;
    const bf16* Bl = g_Wc_lo + (size_t)(ng + g) * H_ + kb;

#pragma unroll 8
    for (int k0 = 0; k0 < KC_; k0 += 16) {
        uint32_t ah[4], al[4], bh[2], bl[2];
        const uint32_t* ph0 = reinterpret_cast<const uint32_t*>(Ah0 + k0);
        const uint32_t* ph1 = reinterpret_cast<const uint32_t*>(Ah1 + k0);
        const uint32_t* pl0 = reinterpret_cast<const uint32_t*>(Al0 + k0);
        const uint32_t* pl1 = reinterpret_cast<const uint32_t*>(Al1 + k0);
        const uint32_t* pbh = reinterpret_cast<const uint32_t*>(Bh + k0);
        const uint32_t* pbl = reinterpret_cast<const uint32_t*>(Bl + k0);
        ah[0] = ph0[tg]; ah[2] = ph0[tg + 4];
        ah[1] = ph1[tg]; ah[3] = ph1[tg + 4];
        al[0] = pl0[tg]; al[2] = pl0[tg + 4];
        al[1] = pl1[tg]; al[3] = pl1[tg + 4];
        bh[0] = pbh[tg]; bh[1] = pbh[tg + 4];
        bl[0] = pbl[tg]; bl[1] = pbl[tg + 4];
        mma16816(acc, ah, bh);
        mma16816(acc, ah, bl);
        mma16816(acc, al, bh);
    }

    float* dst = g_gp + (size_t)ks * B_ * G_;
    const int c0 = ng + 2 * tg;
    dst[(size_t)r0 * G_ + c0]     = acc[0];
    dst[(size_t)r0 * G_ + c0 + 1] = acc[1];
    dst[(size_t)r1 * G_ + c0]     = acc[2];
    dst[(size_t)r1 * G_ + c0 + 1] = acc[3];
}

// ---------------- Phase C2: sum partials + gpre + ghh, LSTM update ----------------
__global__ void __launch_bounds__(256) k_update2(int t) {
    const int tid = threadIdx.x;
    const int b = tid >> 3, jj = tid & 7;
    const int j = blockIdx.x * 8 + jj;
    const float* gpre = g_gates_pre + (size_t)t * B_ * G_ + (size_t)b * G_;

    float gate[4];
#pragma unroll
    for (int qc = 0; qc < 4; qc++) {
        int col = qc * 1024 + j;
        float v = gpre[col];
#pragma unroll
        for (int s = 0; s < KS_; s++) {
            v += g_gp[(size_t)s * B_ * G_ + (size_t)b * G_ + col];
            v += g_qA[(size_t)s * B_ * NA_ + b * NA_ + H_ + col];
        }
        gate[qc] = v;
    }

    float ig = 1.f / (1.f + expf(-gate[0]));
    float fg = 1.f / (1.f + expf(-gate[1]));
    float gg = tanhf(gate[2]);
    float og = 1.f / (1.f + expf(-gate[3]));
    int par = t & 1;
    int idx = b * H_ + j;
    float c = fg * g_c[par][idx] + ig * gg;
    float h = og * tanhf(c);
    g_c[par ^ 1][idx] = c;
    g_h[par ^ 1][idx] = h;
    split_bf(h, g_ctxh_hi[b * 2048 + H_ + j], g_ctxh_lo[b * 2048 + H_ + j]);
    g_Hbf[(size_t)(t * B_ + b) * H_ + j] = __float2bfloat16(h);
}

// ------------------------- in-place log-softmax over V per output row -------------------------
__global__ void __launch_bounds__(256) k_logsoftmax(float* __restrict__ out) {
    __shared__ float red[8];
    __shared__ float bc;
    const int r = blockIdx.x;
    float* x = out + OUT_DEC + (size_t)r * V_;
    const int tid = threadIdx.x, lane = tid & 31, warp = tid >> 5;

    float m = -INFINITY;
    for (int v = tid; v < V_; v += 256) m = fmaxf(m, x[v]);
#pragma unroll
    for (int o2 = 16; o2; o2 >>= 1) m = fmaxf(m, __shfl_xor_sync(0xffffffffu, m, o2));
    if (lane == 0) red[warp] = m;
    __syncthreads();
    if (tid == 0) {
        float mm = red[0];
#pragma unroll
        for (int w = 1; w < 8; w++) mm = fmaxf(mm, red[w]);
        bc = mm;
    }
    __syncthreads();
    m = bc;

    float s = 0.f;
    for (int v = tid; v < V_; v += 256) s += expf(x[v] - m);
#pragma unroll
    for (int o2 = 16; o2; o2 >>= 1) s += __shfl_xor_sync(0xffffffffu, s, o2);
    __syncthreads();
    if (lane == 0) red[warp] = s;
    __syncthreads();
    if (tid == 0) {
        float ss = 0.f;
#pragma unroll
        for (int w = 0; w < 8; w++) ss += red[w];
        bc = m + logf(ss);
    }
    __syncthreads();
    float ls = bc;

    for (int v = tid; v < V_; v += 256) x[v] -= ls;
}

// ------------------------- final state copy -------------------------
__global__ void __launch_bounds__(256) k_final(float* __restrict__ out) {
    int i = blockIdx.x * blockDim.x + threadIdx.x;
    if (i < B_ * H_) {
        out[OUT_HF + i] = g_h[1][i];
        out[OUT_CF + i] = g_c[1][i];
    }
}

// ------------------------- launch -------------------------
extern "C" void kernel_launch(void* const* d_in, const int* in_sizes, int n_in,
                              void* d_out, int out_size) {
    (void)in_sizes; (void)n_in; (void)out_size;
    const float* enc  = (const float*)d_in[0];
    const float* ehid = (const float*)d_in[1];
    const int*   tgt  = (const int*)d_in[2];
    const float* emb  = (const float*)d_in[3];
    const float* Wq   = (const float*)d_in[4];
    const float* bq   = (const float*)d_in[5];
    const float* Wk   = (const float*)d_in[6];
    const float* bk   = (const float*)d_in[7];
    const float* Vw   = (const float*)d_in[8];
    const float* bV   = (const float*)d_in[9];
    const float* Wih  = (const float*)d_in[10];
    const float* Whh  = (const float*)d_in[11];
    const float* bih  = (const float*)d_in[12];
    const float* bhh  = (const float*)d_in[13];
    const float* Wout = (const float*)d_in[14];
    const float* bout = (const float*)d_in[15];
    float* out = (float*)d_out;

    void *p_enc_hi, *p_enc_lo, *p_Wk_hi, *p_Wk_lo, *p_Wx_hi, *p_Wx_lo,
         *p_Wout, *p_X_hi, *p_X_lo, *p_keys, *p_gpre, *p_Hbf, *p_bsum;
    cudaGetSymbolAddress(&p_enc_hi, g_enc_hi);
    cudaGetSymbolAddress(&p_enc_lo, g_enc_lo);
    cudaGetSymbolAddress(&p_Wk_hi, g_Wk_hi);
    cudaGetSymbolAddress(&p_Wk_lo, g_Wk_lo);
    cudaGetSymbolAddress(&p_Wx_hi, g_Wx_hi);
    cudaGetSymbolAddress(&p_Wx_lo, g_Wx_lo);
    cudaGetSymbolAddress(&p_Wout, g_Wout_bf);
    cudaGetSymbolAddress(&p_X_hi, g_X_hi);
    cudaGetSymbolAddress(&p_X_lo, g_X_lo);
    cudaGetSymbolAddress(&p_keys, g_keys);
    cudaGetSymbolAddress(&p_gpre, g_gates_pre);
    cudaGetSymbolAddress(&p_Hbf, g_Hbf);
    cudaGetSymbolAddress(&p_bsum, g_bsum);

    // prep: 2 launches
    k_prep<<<2048, 256>>>(enc, ehid, Wq, Wk, Wih, Whh, bih, bhh, Wout);
    k_gather<<<TB_, 256>>>(emb, tgt);

    // hoisted GEMMs (split precision)
    {   // keys_proj = enc @ Wk^T + bk : [1312,1024]
        dim3 grid((TB_ + 63) / 64, H_ / 128);
        k_gemm2<4, 2, 8><<<grid, 256>>>((const bf16*)p_enc_hi, (const bf16*)p_enc_lo, H_,
                                        (const bf16*)p_Wk_hi, (const bf16*)p_Wk_lo, H_,
                                        (float*)p_keys, H_, bk, TB_, H_, H_);
    }
    {   // gates_pre = X @ Wx^T + (bih+bhh) : [1312,4096]
        dim3 grid((TB_ + 63) / 64, G_ / 128);
        k_gemm2<4, 2, 8><<<grid, 256>>>((const bf16*)p_X_hi, (const bf16*)p_X_lo, H_,
                                        (const bf16*)p_Wx_hi, (const bf16*)p_Wx_lo, H_,
                                        (float*)p_gpre, G_, (const float*)p_bsum, TB_, G_, H_);
    }

    // sequential decode: 5 launches per step, all phases chip-wide
    for (int t = 0; t < T_; t++) {
        k_qghh<<<dim3(KS_, 80), 256>>>();
        k_scores<<<dim3(S_, B_), 128>>>(Vw, bq, bV);
        k_softctx<<<B_, 256>>>(out + OUT_ATTN, t);
        k_gatesmm<<<dim3(KS_, 128), 256>>>();
        k_update2<<<128, 256>>>(t);
    }

    {   // logits -> directly into out[OUT_DEC] at [b,t,:] via remap epilogue
        dim3 grid((TB_ + 63) / 64, V_ / 128);
        k_gemm<4, 2, 8, true><<<grid, 256>>>((const bf16*)p_Hbf, H_, (const bf16*)p_Wout, H_,
                                             out + OUT_DEC, V_, bout, TB_, V_, H_);
    }
    k_logsoftmax<<<TB_, 256>>>(out);
    k_final<<<128, 256>>>(out);
}

// round 12
// speedup vs baseline: 1.5941x; 1.3783x over previous
#include <cuda_runtime.h>
#include <cuda_bf16.h>
#include <cstdint>

using bf16 = __nv_bfloat16;

#define B_  32
#define S_  41
#define T_  41
#define H_  1024
#define V_  16384
#define G_  4096
#define NA_ 5120   // combined q(1024) + ghh(4096)
#define TB_ 1312   // T_*B_

// output layout (flattened concat of reference return values, fp32)
#define OUT_DEC  0ull
#define OUT_HF   21495808ull
#define OUT_CF   21528576ull
#define OUT_ATTN 21561344ull

// ------------------------- device scratch (static, no allocs) -------------------------
__device__ bf16  g_enc_hi[TB_ * H_];
__device__ bf16  g_enc_lo[TB_ * H_];
__device__ float g_encT[B_ * H_ * S_];          // enc transposed [b,h,s]
__device__ bf16  g_Wk_hi[H_ * H_];
__device__ bf16  g_Wk_lo[H_ * H_];
__device__ bf16  g_Wqhh_hi[NA_ * H_];           // rows 0..1023 = Wq; 1024..5119 = Whh
__device__ bf16  g_Wqhh_lo[NA_ * H_];
__device__ bf16  g_Wx_hi[G_ * H_];              // Wih[:, 0:1024]   (x part)
__device__ bf16  g_Wx_lo[G_ * H_];
__device__ bf16  g_Wc_hi[G_ * H_];              // Wih[:, 1024:2048] (ctx part)
__device__ bf16  g_Wc_lo[G_ * H_];
__device__ bf16  g_Wout_bf[(size_t)V_ * H_];
__device__ bf16  g_X_hi[TB_ * H_];
__device__ bf16  g_X_lo[TB_ * H_];
__device__ float g_keys[TB_ * H_];
__device__ float g_gates_pre[(size_t)TB_ * G_]; // X@Wx^T + bih + bhh
__device__ float g_qA[B_ * NA_];                // h@[Wq|Whh]^T
__device__ float g_gp[B_ * G_];                 // ctx@Wc^T
__device__ float g_scores[B_ * S_];             // attention scores per step
__device__ bf16  g_ctxh_hi[B_ * 2 * H_];        // per b: [ctx(1024) | h(1024)]
__device__ bf16  g_ctxh_lo[B_ * 2 * H_];
__device__ float g_h[2][B_ * H_];
__device__ float g_c[2][B_ * H_];
__device__ bf16  g_Hbf[TB_ * H_];
__device__ float g_bsum[G_];

__device__ __forceinline__ void split_bf(float v, bf16& hi, bf16& lo) {
    bf16 h = __float2bfloat16(v);
    hi = h;
    lo = __float2bfloat16(v - __bfloat162float(h));
}

// ------------------------- ONE merged prep kernel (grid-stride segments) -------------------------
__global__ void k_prep(const float* __restrict__ enc, const float* __restrict__ ehid,
                       const float* __restrict__ Wq, const float* __restrict__ Wk,
                       const float* __restrict__ Wih, const float* __restrict__ Whh,
                       const float* __restrict__ bih, const float* __restrict__ bhh,
                       const float* __restrict__ Wout) {
    const int stride = gridDim.x * blockDim.x;
    const int tid0 = blockIdx.x * blockDim.x + threadIdx.x;

    for (int i = tid0; i < TB_ * H_; i += stride)
        split_bf(enc[i], g_enc_hi[i], g_enc_lo[i]);
    for (int i = tid0; i < B_ * S_ * H_; i += stride) {
        int h = i & 1023;
        int row = i >> 10;          // b*S_+s
        int s = row % S_;
        int bb = row / S_;
        g_encT[((size_t)bb * H_ + h) * S_ + s] = enc[i];
    }
    for (int i = tid0; i < H_ * H_; i += stride)
        split_bf(Wk[i], g_Wk_hi[i], g_Wk_lo[i]);
    for (size_t i = tid0; i < (size_t)V_ * H_; i += stride)
        g_Wout_bf[i] = __float2bfloat16(Wout[i]);
    for (int i = tid0; i < NA_ * H_; i += stride) {
        int n = i >> 10, k = i & 1023;
        float v = (n < 1024) ? Wq[(size_t)n * H_ + k] : Whh[(size_t)(n - 1024) * H_ + k];
        split_bf(v, g_Wqhh_hi[i], g_Wqhh_lo[i]);
    }
    for (int i = tid0; i < G_ * H_; i += stride) {
        int n = i >> 10, k = i & 1023;
        split_bf(Wih[(size_t)n * 2048 + k], g_Wx_hi[i], g_Wx_lo[i]);
    }
    for (int i = tid0; i < G_ * H_; i += stride) {
        int n = i >> 10, k = i & 1023;
        split_bf(Wih[(size_t)n * 2048 + 1024 + k], g_Wc_hi[i], g_Wc_lo[i]);
    }
    for (int i = tid0; i < G_; i += stride)
        g_bsum[i] = bih[i] + bhh[i];
    for (int i = tid0; i < B_ * H_; i += stride) {
        float h = ehid[i];
        g_c[0][i] = 0.f;
        g_h[0][i] = h;
        int b = i >> 10, j = i & 1023;
        split_bf(h, g_ctxh_hi[b * 2048 + 1024 + j], g_ctxh_lo[b * 2048 + 1024 + j]);
    }
}

// NOTE: target_tensor is int32 on the wire (JAX downcasts int64 without x64 mode).
__global__ void k_gather(const float* __restrict__ emb, const int* __restrict__ tgt) {
    int r = blockIdx.x;             // r = t*32 + b
    int t = r >> 5, b = r & 31;
    int tok = (t == 0) ? 0 : tgt[b * 41 + (t - 1)];
    tok &= (V_ - 1);
    const float* src = emb + (size_t)tok * H_;
    for (int h = threadIdx.x; h < H_; h += blockDim.x)
        split_bf(src[h], g_X_hi[(size_t)r * H_ + h], g_X_lo[(size_t)r * H_ + h]);
}

// ------------------------- MMA primitive -------------------------
__device__ __forceinline__ void mma16816(float* c, const uint32_t* a, const uint32_t* b) {
    asm volatile(
        "mma.sync.aligned.m16n8k16.row.col.f32.bf16.bf16.f32 "
        "{%0,%1,%2,%3}, {%4,%5,%6,%7}, {%8,%9}, {%0,%1,%2,%3};"
        : "+f"(c[0]), "+f"(c[1]), "+f"(c[2]), "+f"(c[3])
        : "r"(a[0]), "r"(a[1]), "r"(a[2]), "r"(a[3]), "r"(b[0]), "r"(b[1]));
}

// =================== smem-tiled GEMM: C[M,N] = (Ah+Al) @ (Bh+Bl)^T (+bias) ===================
// Block tile 64(M) x 128(N), K-chunk 64. Global->smem via coalesced uint4 (16B),
// fragments via bank-conflict-free LDS.32 (row stride 72 bf16 = 36 u32).
// SPLIT: Markidis 3-MMA split-bf16 (~fp32). REMAP: out row r=t*32+b -> b*T+t.
// Shared memory is DYNAMIC (55296B for SPLIT > 48KB static limit).
#define KC64 64
#define AST 72          // smem row stride in bf16
#define ASTW 36         // in u32
#define SMEM_SPLIT ((64 + 128) * AST * 2 * 2)   // 55296 B
#define SMEM_SINGLE ((64 + 128) * AST * 2)      // 27648 B

template <bool SPLIT, bool REMAP>
__global__ void __launch_bounds__(256)
k_gemm_sm(const bf16* __restrict__ Ah, const bf16* __restrict__ Al, int lda,
          const bf16* __restrict__ Bh, const bf16* __restrict__ Bl, int ldb,
          float* __restrict__ C, int ldc,
          const float* __restrict__ bias,
          int M, int N, int K) {
    extern __shared__ bf16 smem[];
    bf16* sAh = smem;                                   // 64*AST
    bf16* sBh = smem + 64 * AST;                        // 128*AST
    bf16* sAl = SPLIT ? (smem + (64 + 128) * AST) : nullptr;
    bf16* sBl = SPLIT ? (smem + (64 + 128) * AST + 64 * AST) : nullptr;

    const int tid = threadIdx.x, lane = tid & 31, warp = tid >> 5;
    const int g = lane >> 2, tg = lane & 3;
    const int m0 = blockIdx.x * 64;
    const int n0blk = blockIdx.y * 128;
    const int nw = warp * 16;

    float acc[4][2][4];
#pragma unroll
    for (int i = 0; i < 4; i++)
#pragma unroll
        for (int j = 0; j < 2; j++)
#pragma unroll
            for (int q = 0; q < 4; q++) acc[i][j][q] = 0.f;

    for (int k0 = 0; k0 < K; k0 += KC64) {
        __syncthreads();
        // ---- load A tile: 64 rows x 8 uint4 ----
#pragma unroll
        for (int it = 0; it < 2; it++) {
            int idx = tid + it * 256;
            int r = idx >> 3, c = idx & 7;
            int ga = m0 + r; if (ga >= M) ga = M - 1;
            const uint4* src = reinterpret_cast<const uint4*>(Ah + (size_t)ga * lda + k0);
            *reinterpret_cast<uint4*>(sAh + r * AST + c * 8) = src[c];
            if (SPLIT) {
                const uint4* srcl = reinterpret_cast<const uint4*>(Al + (size_t)ga * lda + k0);
                *reinterpret_cast<uint4*>(sAl + r * AST + c * 8) = srcl[c];
            }
        }
        // ---- load B tile: 128 rows x 8 uint4 ----
#pragma unroll
        for (int it = 0; it < 4; it++) {
            int idx = tid + it * 256;
            int r = idx >> 3, c = idx & 7;
            int gb = n0blk + r;
            const uint4* src = reinterpret_cast<const uint4*>(Bh + (size_t)gb * ldb + k0);
            *reinterpret_cast<uint4*>(sBh + r * AST + c * 8) = src[c];
            if (SPLIT) {
                const uint4* srcl = reinterpret_cast<const uint4*>(Bl + (size_t)gb * ldb + k0);
                *reinterpret_cast<uint4*>(sBl + r * AST + c * 8) = srcl[c];
            }
        }
        __syncthreads();

        const uint32_t* sa  = reinterpret_cast<const uint32_t*>(sAh);
        const uint32_t* sb  = reinterpret_cast<const uint32_t*>(sBh);
        const uint32_t* sal = reinterpret_cast<const uint32_t*>(sAl);
        const uint32_t* sbl = reinterpret_cast<const uint32_t*>(sBl);

#pragma unroll
        for (int s = 0; s < 4; s++) {        // four k16 steps per chunk
            uint32_t a_[4][4], b_[2][2];
#pragma unroll
            for (int i = 0; i < 4; i++) {
                int r0 = 16 * i + g, r1 = r0 + 8;
                a_[i][0] = sa[r0 * ASTW + s * 8 + tg];
                a_[i][2] = sa[r0 * ASTW + s * 8 + tg + 4];
                a_[i][1] = sa[r1 * ASTW + s * 8 + tg];
                a_[i][3] = sa[r1 * ASTW + s * 8 + tg + 4];
            }
#pragma unroll
            for (int j = 0; j < 2; j++) {
                int n = nw + 8 * j + g;
                b_[j][0] = sb[n * ASTW + s * 8 + tg];
                b_[j][1] = sb[n * ASTW + s * 8 + tg + 4];
            }
#pragma unroll
            for (int i = 0; i < 4; i++)
#pragma unroll
                for (int j = 0; j < 2; j++) mma16816(acc[i][j], a_[i], b_[j]);

            if (SPLIT) {
                uint32_t al_[4][4], bl_[2][2];
#pragma unroll
                for (int i = 0; i < 4; i++) {
                    int r0 = 16 * i + g, r1 = r0 + 8;
                    al_[i][0] = sal[r0 * ASTW + s * 8 + tg];
                    al_[i][2] = sal[r0 * ASTW + s * 8 + tg + 4];
                    al_[i][1] = sal[r1 * ASTW + s * 8 + tg];
                    al_[i][3] = sal[r1 * ASTW + s * 8 + tg + 4];
                }
#pragma unroll
                for (int j = 0; j < 2; j++) {
                    int n = nw + 8 * j + g;
                    bl_[j][0] = sbl[n * ASTW + s * 8 + tg];
                    bl_[j][1] = sbl[n * ASTW + s * 8 + tg + 4];
                }
#pragma unroll
                for (int i = 0; i < 4; i++)
#pragma unroll
                    for (int j = 0; j < 2; j++) {
                        mma16816(acc[i][j], a_[i], bl_[j]);
                        mma16816(acc[i][j], al_[i], b_[j]);
                    }
            }
        }
    }

    // ---- epilogue ----
#pragma unroll
    for (int i = 0; i < 4; i++) {
        int r0 = m0 + 16 * i + g;
        int r1 = r0 + 8;
        size_t or0 = REMAP ? ((size_t)(r0 & 31) * T_ + (r0 >> 5)) : (size_t)r0;
        size_t or1 = REMAP ? ((size_t)(r1 & 31) * T_ + (r1 >> 5)) : (size_t)r1;
#pragma unroll
        for (int j = 0; j < 2; j++) {
            int c0 = n0blk + nw + 8 * j + 2 * tg;
            float v0 = acc[i][j][0], v1 = acc[i][j][1], v2 = acc[i][j][2], v3 = acc[i][j][3];
            if (bias) {
                float bb0 = bias[c0], bb1 = bias[c0 + 1];
                v0 += bb0; v1 += bb1; v2 += bb0; v3 += bb1;
            }
            if (r0 < M) { C[or0 * ldc + c0] = v0; C[or0 * ldc + c0 + 1] = v1; }
            if (r1 < M) { C[or1 * ldc + c0] = v2; C[or1 * ldc + c0 + 1] = v3; }
        }
    }
}

// ============ Phase B1: scores — one block per (s,b), chip-wide MUFU spread ============
__global__ void __launch_bounds__(128) k_scores(const float* __restrict__ Vw,
                                                const float* __restrict__ bq,
                                                const float* __restrict__ bV) {
    const int s = blockIdx.x, b = blockIdx.y;
    const int tid = threadIdx.x, lane = tid & 31, warp = tid >> 5;
    __shared__ float red[4];

    const float* kp = g_keys + ((size_t)b * S_ + s) * H_;
    float a = 0.f;
    for (int h = tid; h < H_; h += 128) {
        float q = bq[h] + g_qA[b * NA_ + h];
        a += tanhf(q + kp[h]) * Vw[h];
    }
#pragma unroll
    for (int o = 16; o; o >>= 1) a += __shfl_xor_sync(0xffffffffu, a, o);
    if (lane == 0) red[warp] = a;
    __syncthreads();
    if (tid == 0)
        g_scores[b * S_ + s] = red[0] + red[1] + red[2] + red[3] + bV[0];
}

// ============ Phase B2: softmax + attn output + ctx (32 blocks) ============
__global__ void __launch_bounds__(256) k_softctx(float* __restrict__ out_attn, int t) {
    __shared__ float ssc[48];
    const int b = blockIdx.x, tid = threadIdx.x;
    const int warp = tid >> 5, lane = tid & 31;

    if (warp == 0) {
        float v0 = g_scores[b * S_ + ((lane < S_) ? lane : 0)];
        if (lane >= S_) v0 = -INFINITY;
        float v1 = (lane < S_ - 32) ? g_scores[b * S_ + lane + 32] : -INFINITY;
        float m = fmaxf(v0, v1);
#pragma unroll
        for (int o = 16; o; o >>= 1) m = fmaxf(m, __shfl_xor_sync(0xffffffffu, m, o));
        float e0 = (lane < S_) ? expf(v0 - m) : 0.f;
        float e1 = (lane < S_ - 32) ? expf(v1 - m) : 0.f;
        float s = e0 + e1;
#pragma unroll
        for (int o = 16; o; o >>= 1) s += __shfl_xor_sync(0xffffffffu, s, o);
        float inv = 1.f / s;
        if (lane < S_) {
            float w0 = e0 * inv;
            ssc[lane] = w0;
            out_attn[((size_t)b * T_ + t) * S_ + lane] = w0;
        }
        if (lane < S_ - 32) {
            float w1 = e1 * inv;
            ssc[lane + 32] = w1;
            out_attn[((size_t)b * T_ + t) * S_ + lane + 32] = w1;
        }
    }
    __syncthreads();

    for (int h = tid; h < H_; h += 256) {
        const float* ep = g_encT + ((size_t)b * H_ + h) * S_;
        float a = 0.f;
#pragma unroll
        for (int s = 0; s < S_; s++) a += ssc[s] * ep[s];
        split_bf(a, g_ctxh_hi[b * 2048 + h], g_ctxh_lo[b * 2048 + h]);
    }
}

// ---------------- Phase C2: gates sum + LSTM update ----------------
__global__ void __launch_bounds__(256) k_update2(int t) {
    const int tid = threadIdx.x;
    const int b = tid >> 3, jj = tid & 7;
    const int j = blockIdx.x * 8 + jj;
    const float* gpre = g_gates_pre + (size_t)t * B_ * G_ + (size_t)b * G_;

    float gate[4];
#pragma unroll
    for (int qc = 0; qc < 4; qc++) {
        int col = qc * 1024 + j;
        gate[qc] = gpre[col] + g_gp[(size_t)b * G_ + col] + g_qA[b * NA_ + H_ + col];
    }

    float ig = 1.f / (1.f + expf(-gate[0]));
    float fg = 1.f / (1.f + expf(-gate[1]));
    float gg = tanhf(gate[2]);
    float og = 1.f / (1.f + expf(-gate[3]));
    int par = t & 1;
    int idx = b * H_ + j;
    float c = fg * g_c[par][idx] + ig * gg;
    float h = og * tanhf(c);
    g_c[par ^ 1][idx] = c;
    g_h[par ^ 1][idx] = h;
    split_bf(h, g_ctxh_hi[b * 2048 + H_ + j], g_ctxh_lo[b * 2048 + H_ + j]);
    g_Hbf[(size_t)(t * B_ + b) * H_ + j] = __float2bfloat16(h);
}

// ------------------------- in-place log-softmax over V per output row -------------------------
__global__ void __launch_bounds__(256) k_logsoftmax(float* __restrict__ out) {
    __shared__ float red[8];
    __shared__ float bc;
    const int r = blockIdx.x;
    float* x = out + OUT_DEC + (size_t)r * V_;
    const int tid = threadIdx.x, lane = tid & 31, warp = tid >> 5;

    float m = -INFINITY;
    for (int v = tid; v < V_; v += 256) m = fmaxf(m, x[v]);
#pragma unroll
    for (int o2 = 16; o2; o2 >>= 1) m = fmaxf(m, __shfl_xor_sync(0xffffffffu, m, o2));
    if (lane == 0) red[warp] = m;
    __syncthreads();
    if (tid == 0) {
        float mm = red[0];
#pragma unroll
        for (int w = 1; w < 8; w++) mm = fmaxf(mm, red[w]);
        bc = mm;
    }
    __syncthreads();
    m = bc;

    float s = 0.f;
    for (int v = tid; v < V_; v += 256) s += expf(x[v] - m);
#pragma unroll
    for (int o2 = 16; o2; o2 >>= 1) s += __shfl_xor_sync(0xffffffffu, s, o2);
    __syncthreads();
    if (lane == 0) red[warp] = s;
    __syncthreads();
    if (tid == 0) {
        float ss = 0.f;
#pragma unroll
        for (int w = 0; w < 8; w++) ss += red[w];
        bc = m + logf(ss);
    }
    __syncthreads();
    float ls = bc;

    for (int v = tid; v < V_; v += 256) x[v] -= ls;
}

// ------------------------- final state copy -------------------------
__global__ void __launch_bounds__(256) k_final(float* __restrict__ out) {
    int i = blockIdx.x * blockDim.x + threadIdx.x;
    if (i < B_ * H_) {
        out[OUT_HF + i] = g_h[1][i];
        out[OUT_CF + i] = g_c[1][i];
    }
}

// ------------------------- launch -------------------------
extern "C" void kernel_launch(void* const* d_in, const int* in_sizes, int n_in,
                              void* d_out, int out_size) {
    (void)in_sizes; (void)n_in; (void)out_size;
    const float* enc  = (const float*)d_in[0];
    const float* ehid = (const float*)d_in[1];
    const int*   tgt  = (const int*)d_in[2];
    const float* emb  = (const float*)d_in[3];
    const float* Wq   = (const float*)d_in[4];
    const float* bq   = (const float*)d_in[5];
    const float* Wk   = (const float*)d_in[6];
    const float* bk   = (const float*)d_in[7];
    const float* Vw   = (const float*)d_in[8];
    const float* bV   = (const float*)d_in[9];
    const float* Wih  = (const float*)d_in[10];
    const float* Whh  = (const float*)d_in[11];
    const float* bih  = (const float*)d_in[12];
    const float* bhh  = (const float*)d_in[13];
    const float* Wout = (const float*)d_in[14];
    const float* bout = (const float*)d_in[15];
    float* out = (float*)d_out;

    // opt-in to >48KB dynamic smem (idempotent; not an allocation)
    static bool attr_done = false;
    if (!attr_done) {
        cudaFuncSetAttribute((const void*)k_gemm_sm<true, false>,
                             cudaFuncAttributeMaxDynamicSharedMemorySize, SMEM_SPLIT);
        cudaFuncSetAttribute((const void*)k_gemm_sm<false, true>,
                             cudaFuncAttributeMaxDynamicSharedMemorySize, SMEM_SINGLE);
        attr_done = true;
    }

    void *p_enc_hi, *p_enc_lo, *p_Wk_hi, *p_Wk_lo, *p_Wqhh_hi, *p_Wqhh_lo,
         *p_Wx_hi, *p_Wx_lo, *p_Wc_hi, *p_Wc_lo, *p_Wout, *p_X_hi, *p_X_lo,
         *p_keys, *p_gpre, *p_qA, *p_gp, *p_ch_hi, *p_ch_lo, *p_Hbf, *p_bsum;
    cudaGetSymbolAddress(&p_enc_hi, g_enc_hi);
    cudaGetSymbolAddress(&p_enc_lo, g_enc_lo);
    cudaGetSymbolAddress(&p_Wk_hi, g_Wk_hi);
    cudaGetSymbolAddress(&p_Wk_lo, g_Wk_lo);
    cudaGetSymbolAddress(&p_Wqhh_hi, g_Wqhh_hi);
    cudaGetSymbolAddress(&p_Wqhh_lo, g_Wqhh_lo);
    cudaGetSymbolAddress(&p_Wx_hi, g_Wx_hi);
    cudaGetSymbolAddress(&p_Wx_lo, g_Wx_lo);
    cudaGetSymbolAddress(&p_Wc_hi, g_Wc_hi);
    cudaGetSymbolAddress(&p_Wc_lo, g_Wc_lo);
    cudaGetSymbolAddress(&p_Wout, g_Wout_bf);
    cudaGetSymbolAddress(&p_X_hi, g_X_hi);
    cudaGetSymbolAddress(&p_X_lo, g_X_lo);
    cudaGetSymbolAddress(&p_keys, g_keys);
    cudaGetSymbolAddress(&p_gpre, g_gates_pre);
    cudaGetSymbolAddress(&p_qA, g_qA);
    cudaGetSymbolAddress(&p_gp, g_gp);
    cudaGetSymbolAddress(&p_ch_hi, g_ctxh_hi);
    cudaGetSymbolAddress(&p_ch_lo, g_ctxh_lo);
    cudaGetSymbolAddress(&p_Hbf, g_Hbf);
    cudaGetSymbolAddress(&p_bsum, g_bsum);

    // prep: 2 launches
    k_prep<<<2048, 256>>>(enc, ehid, Wq, Wk, Wih, Whh, bih, bhh, Wout);
    k_gather<<<TB_, 256>>>(emb, tgt);

    // hoisted GEMMs (split precision, smem-tiled)
    {   // keys_proj = enc @ Wk^T + bk : [1312,1024]
        dim3 grid((TB_ + 63) / 64, H_ / 128);
        k_gemm_sm<true, false><<<grid, 256, SMEM_SPLIT>>>(
            (const bf16*)p_enc_hi, (const bf16*)p_enc_lo, H_,
            (const bf16*)p_Wk_hi, (const bf16*)p_Wk_lo, H_,
            (float*)p_keys, H_, bk, TB_, H_, H_);
    }
    {   // gates_pre = X @ Wx^T + (bih+bhh) : [1312,4096]
        dim3 grid((TB_ + 63) / 64, G_ / 128);
        k_gemm_sm<true, false><<<grid, 256, SMEM_SPLIT>>>(
            (const bf16*)p_X_hi, (const bf16*)p_X_lo, H_,
            (const bf16*)p_Wx_hi, (const bf16*)p_Wx_lo, H_,
            (float*)p_gpre, G_, (const float*)p_bsum, TB_, G_, H_);
    }

    // sequential decode: 5 launches per step
    for (int t = 0; t < T_; t++) {
        {   // qghh = h @ [Wq|Whh]^T : [32,5120]
            dim3 grid(1, NA_ / 128);
            k_gemm_sm<true, false><<<grid, 256, SMEM_SPLIT>>>(
                (const bf16*)p_ch_hi + H_, (const bf16*)p_ch_lo + H_, 2 * H_,
                (const bf16*)p_Wqhh_hi, (const bf16*)p_Wqhh_lo, H_,
                (float*)p_qA, NA_, nullptr, B_, NA_, H_);
        }
        k_scores<<<dim3(S_, B_), 128>>>(Vw, bq, bV);
        k_softctx<<<B_, 256>>>(out + OUT_ATTN, t);
        {   // gates_ctx = ctx @ Wc^T : [32,4096]
            dim3 grid(1, G_ / 128);
            k_gemm_sm<true, false><<<grid, 256, SMEM_SPLIT>>>(
                (const bf16*)p_ch_hi, (const bf16*)p_ch_lo, 2 * H_,
                (const bf16*)p_Wc_hi, (const bf16*)p_Wc_lo, H_,
                (float*)p_gp, G_, nullptr, B_, G_, H_);
        }
        k_update2<<<128, 256>>>(t);
    }

    {   // logits -> directly into out[OUT_DEC] at [b,t,:] via remap epilogue (single bf16)
        dim3 grid((TB_ + 63) / 64, V_ / 128);
        k_gemm_sm<false, true><<<grid, 256, SMEM_SINGLE>>>(
            (const bf16*)p_Hbf, nullptr, H_,
            (const bf16*)p_Wout, nullptr, H_,
            out + OUT_DEC, V_, bout, TB_, V_, H_);
    }
    k_logsoftmax<<<TB_, 256>>>(out);
    k_final<<<128, 256>>>(out);
}

// round 13
// speedup vs baseline: 2.6278x; 1.6485x over previous
#include <cuda_runtime.h>
#include <cuda_bf16.h>
#include <cstdint>

using bf16 = __nv_bfloat16;

#define B_  32
#define S_  41
#define T_  41
#define H_  1024
#define V_  16384
#define G_  4096
#define NA_ 5120   // combined q(1024) + ghh(4096)
#define TB_ 1312   // T_*B_
#define KS_ 4      // split-K for per-step GEMMs
#define KC_ (H_ / KS_)

// output layout (flattened concat of reference return values, fp32)
#define OUT_DEC  0ull
#define OUT_HF   21495808ull
#define OUT_CF   21528576ull
#define OUT_ATTN 21561344ull

// ------------------------- device scratch (static, no allocs) -------------------------
__device__ bf16  g_enc_hi[TB_ * H_];
__device__ bf16  g_enc_lo[TB_ * H_];
__device__ float g_encT[B_ * H_ * S_];          // enc transposed [b,h,s]
__device__ bf16  g_Wk_hi[H_ * H_];
__device__ bf16  g_Wk_lo[H_ * H_];
__device__ bf16  g_Wqhh_hi[NA_ * H_];           // rows 0..1023 = Wq; 1024..5119 = Whh
__device__ bf16  g_Wqhh_lo[NA_ * H_];
__device__ bf16  g_Wx_hi[G_ * H_];              // Wih[:, 0:1024]   (x part)
__device__ bf16  g_Wx_lo[G_ * H_];
__device__ bf16  g_Wc_hi[G_ * H_];              // Wih[:, 1024:2048] (ctx part)
__device__ bf16  g_Wc_lo[G_ * H_];
__device__ bf16  g_Wout_bf[(size_t)V_ * H_];
__device__ bf16  g_X_hi[TB_ * H_];
__device__ bf16  g_X_lo[TB_ * H_];
__device__ float g_keys[TB_ * H_];
__device__ float g_gates_pre[(size_t)TB_ * G_]; // X@Wx^T + bih + bhh
__device__ float g_qA[KS_ * B_ * NA_];          // split-K partials of h@[Wq|Whh]^T
__device__ float g_gp[KS_ * B_ * G_];           // split-K partials of ctx@Wc^T
__device__ float g_scores[B_ * S_];             // attention scores per step
__device__ bf16  g_ctxh_hi[B_ * 2 * H_];        // per b: [ctx(1024) | h(1024)]
__device__ bf16  g_ctxh_lo[B_ * 2 * H_];
__device__ float g_h[2][B_ * H_];
__device__ float g_c[2][B_ * H_];
__device__ bf16  g_Hbf[TB_ * H_];
__device__ float g_bsum[G_];

__device__ __forceinline__ void split_bf(float v, bf16& hi, bf16& lo) {
    bf16 h = __float2bfloat16(v);
    hi = h;
    lo = __float2bfloat16(v - __bfloat162float(h));
}

// ------------------------- ONE merged prep kernel (grid-stride segments) -------------------------
__global__ void k_prep(const float* __restrict__ enc, const float* __restrict__ ehid,
                       const float* __restrict__ Wq, const float* __restrict__ Wk,
                       const float* __restrict__ Wih, const float* __restrict__ Whh,
                       const float* __restrict__ bih, const float* __restrict__ bhh,
                       const float* __restrict__ Wout) {
    const int stride = gridDim.x * blockDim.x;
    const int tid0 = blockIdx.x * blockDim.x + threadIdx.x;

    for (int i = tid0; i < TB_ * H_; i += stride)
        split_bf(enc[i], g_enc_hi[i], g_enc_lo[i]);
    for (int i = tid0; i < B_ * S_ * H_; i += stride) {
        int h = i & 1023;
        int row = i >> 10;          // b*S_+s
        int s = row % S_;
        int bb = row / S_;
        g_encT[((size_t)bb * H_ + h) * S_ + s] = enc[i];
    }
    for (int i = tid0; i < H_ * H_; i += stride)
        split_bf(Wk[i], g_Wk_hi[i], g_Wk_lo[i]);
    for (size_t i = tid0; i < (size_t)V_ * H_; i += stride)
        g_Wout_bf[i] = __float2bfloat16(Wout[i]);
    for (int i = tid0; i < NA_ * H_; i += stride) {
        int n = i >> 10, k = i & 1023;
        float v = (n < 1024) ? Wq[(size_t)n * H_ + k] : Whh[(size_t)(n - 1024) * H_ + k];
        split_bf(v, g_Wqhh_hi[i], g_Wqhh_lo[i]);
    }
    for (int i = tid0; i < G_ * H_; i += stride) {
        int n = i >> 10, k = i & 1023;
        split_bf(Wih[(size_t)n * 2048 + k], g_Wx_hi[i], g_Wx_lo[i]);
    }
    for (int i = tid0; i < G_ * H_; i += stride) {
        int n = i >> 10, k = i & 1023;
        split_bf(Wih[(size_t)n * 2048 + 1024 + k], g_Wc_hi[i], g_Wc_lo[i]);
    }
    for (int i = tid0; i < G_; i += stride)
        g_bsum[i] = bih[i] + bhh[i];
    for (int i = tid0; i < B_ * H_; i += stride) {
        float h = ehid[i];
        g_c[0][i] = 0.f;
        g_h[0][i] = h;
        int b = i >> 10, j = i & 1023;
        split_bf(h, g_ctxh_hi[b * 2048 + 1024 + j], g_ctxh_lo[b * 2048 + 1024 + j]);
    }
}

// NOTE: target_tensor is int32 on the wire (JAX downcasts int64 without x64 mode).
__global__ void k_gather(const float* __restrict__ emb, const int* __restrict__ tgt) {
    int r = blockIdx.x;             // r = t*32 + b
    int t = r >> 5, b = r & 31;
    int tok = (t == 0) ? 0 : tgt[b * 41 + (t - 1)];
    tok &= (V_ - 1);
    const float* src = emb + (size_t)tok * H_;
    for (int h = threadIdx.x; h < H_; h += blockDim.x)
        split_bf(src[h], g_X_hi[(size_t)r * H_ + h], g_X_lo[(size_t)r * H_ + h]);
}

// ------------------------- MMA primitive -------------------------
__device__ __forceinline__ void mma16816(float* c, const uint32_t* a, const uint32_t* b) {
    asm volatile(
        "mma.sync.aligned.m16n8k16.row.col.f32.bf16.bf16.f32 "
        "{%0,%1,%2,%3}, {%4,%5,%6,%7}, {%8,%9}, {%0,%1,%2,%3};"
        : "+f"(c[0]), "+f"(c[1]), "+f"(c[2]), "+f"(c[3])
        : "r"(a[0]), "r"(a[1]), "r"(a[2]), "r"(a[3]), "r"(b[0]), "r"(b[1]));
}

// =================== smem-tiled GEMM: C[M,N] = (Ah+Al) @ (Bh+Bl)^T (+bias) ===================
// Block tile 64(M) x 128(N), K-chunk 64. Global->smem via coalesced uint4 (16B),
// fragments via bank-conflict-free LDS.32 (row stride 72 bf16 = 36 u32).
// SPLIT: Markidis 3-MMA split-bf16 (~fp32). REMAP: out row r=t*32+b -> b*T+t.
// blockIdx.z = K-split slice: operands offset by z*K, output by z*zstrideC.
#define KC64 64
#define AST 72          // smem row stride in bf16
#define ASTW 36         // in u32
#define SMEM_SPLIT ((64 + 128) * AST * 2 * 2)   // 55296 B
#define SMEM_SINGLE ((64 + 128) * AST * 2)      // 27648 B

template <bool SPLIT, bool REMAP>
__global__ void __launch_bounds__(256)
k_gemm_sm(const bf16* __restrict__ Ah, const bf16* __restrict__ Al, int lda,
          const bf16* __restrict__ Bh, const bf16* __restrict__ Bl, int ldb,
          float* __restrict__ C, int ldc,
          const float* __restrict__ bias,
          int M, int N, int K, size_t zstrideC) {
    extern __shared__ bf16 smem[];
    bf16* sAh = smem;                                   // 64*AST
    bf16* sBh = smem + 64 * AST;                        // 128*AST
    bf16* sAl = SPLIT ? (smem + (64 + 128) * AST) : nullptr;
    bf16* sBl = SPLIT ? (smem + (64 + 128) * AST + 64 * AST) : nullptr;

    // K-split slice offsets
    {
        const int kz = blockIdx.z * K;
        Ah += kz; Bh += kz;
        if (SPLIT) { Al += kz; Bl += kz; }
        C += (size_t)blockIdx.z * zstrideC;
    }

    const int tid = threadIdx.x, lane = tid & 31, warp = tid >> 5;
    const int g = lane >> 2, tg = lane & 3;
    const int m0 = blockIdx.x * 64;
    const int n0blk = blockIdx.y * 128;
    const int nw = warp * 16;

    float acc[4][2][4];
#pragma unroll
    for (int i = 0; i < 4; i++)
#pragma unroll
        for (int j = 0; j < 2; j++)
#pragma unroll
            for (int q = 0; q < 4; q++) acc[i][j][q] = 0.f;

    for (int k0 = 0; k0 < K; k0 += KC64) {
        __syncthreads();
        // ---- load A tile: 64 rows x 8 uint4 ----
#pragma unroll
        for (int it = 0; it < 2; it++) {
            int idx = tid + it * 256;
            int r = idx >> 3, c = idx & 7;
            int ga = m0 + r; if (ga >= M) ga = M - 1;
            const uint4* src = reinterpret_cast<const uint4*>(Ah + (size_t)ga * lda + k0);
            *reinterpret_cast<uint4*>(sAh + r * AST + c * 8) = src[c];
            if (SPLIT) {
                const uint4* srcl = reinterpret_cast<const uint4*>(Al + (size_t)ga * lda + k0);
                *reinterpret_cast<uint4*>(sAl + r * AST + c * 8) = srcl[c];
            }
        }
        // ---- load B tile: 128 rows x 8 uint4 ----
#pragma unroll
        for (int it = 0; it < 4; it++) {
            int idx = tid + it * 256;
            int r = idx >> 3, c = idx & 7;
            int gb = n0blk + r;
            const uint4* src = reinterpret_cast<const uint4*>(Bh + (size_t)gb * ldb + k0);
            *reinterpret_cast<uint4*>(sBh + r * AST + c * 8) = src[c];
            if (SPLIT) {
                const uint4* srcl = reinterpret_cast<const uint4*>(Bl + (size_t)gb * ldb + k0);
                *reinterpret_cast<uint4*>(sBl + r * AST + c * 8) = srcl[c];
            }
        }
        __syncthreads();

        const uint32_t* sa  = reinterpret_cast<const uint32_t*>(sAh);
        const uint32_t* sb  = reinterpret_cast<const uint32_t*>(sBh);
        const uint32_t* sal = reinterpret_cast<const uint32_t*>(sAl);
        const uint32_t* sbl = reinterpret_cast<const uint32_t*>(sBl);

#pragma unroll
        for (int s = 0; s < 4; s++) {        // four k16 steps per chunk
            uint32_t a_[4][4], b_[2][2];
#pragma unroll
            for (int i = 0; i < 4; i++) {
                int r0 = 16 * i + g, r1 = r0 + 8;
                a_[i][0] = sa[r0 * ASTW + s * 8 + tg];
                a_[i][2] = sa[r0 * ASTW + s * 8 + tg + 4];
                a_[i][1] = sa[r1 * ASTW + s * 8 + tg];
                a_[i][3] = sa[r1 * ASTW + s * 8 + tg + 4];
            }
#pragma unroll
            for (int j = 0; j < 2; j++) {
                int n = nw + 8 * j + g;
                b_[j][0] = sb[n * ASTW + s * 8 + tg];
                b_[j][1] = sb[n * ASTW + s * 8 + tg + 4];
            }
#pragma unroll
            for (int i = 0; i < 4; i++)
#pragma unroll
                for (int j = 0; j < 2; j++) mma16816(acc[i][j], a_[i], b_[j]);

            if (SPLIT) {
                uint32_t al_[4][4], bl_[2][2];
#pragma unroll
                for (int i = 0; i < 4; i++) {
                    int r0 = 16 * i + g, r1 = r0 + 8;
                    al_[i][0] = sal[r0 * ASTW + s * 8 + tg];
                    al_[i][2] = sal[r0 * ASTW + s * 8 + tg + 4];
                    al_[i][1] = sal[r1 * ASTW + s * 8 + tg];
                    al_[i][3] = sal[r1 * ASTW + s * 8 + tg + 4];
                }
#pragma unroll
                for (int j = 0; j < 2; j++) {
                    int n = nw + 8 * j + g;
                    bl_[j][0] = sbl[n * ASTW + s * 8 + tg];
                    bl_[j][1] = sbl[n * ASTW + s * 8 + tg + 4];
                }
#pragma unroll
                for (int i = 0; i < 4; i++)
#pragma unroll
                    for (int j = 0; j < 2; j++) {
                        mma16816(acc[i][j], a_[i], bl_[j]);
                        mma16816(acc[i][j], al_[i], b_[j]);
                    }
            }
        }
    }

    // ---- epilogue ----
#pragma unroll
    for (int i = 0; i < 4; i++) {
        int r0 = m0 + 16 * i + g;
        int r1 = r0 + 8;
        size_t or0 = REMAP ? ((size_t)(r0 & 31) * T_ + (r0 >> 5)) : (size_t)r0;
        size_t or1 = REMAP ? ((size_t)(r1 & 31) * T_ + (r1 >> 5)) : (size_t)r1;
#pragma unroll
        for (int j = 0; j < 2; j++) {
            int c0 = n0blk + nw + 8 * j + 2 * tg;
            float v0 = acc[i][j][0], v1 = acc[i][j][1], v2 = acc[i][j][2], v3 = acc[i][j][3];
            if (bias) {
                float bb0 = bias[c0], bb1 = bias[c0 + 1];
                v0 += bb0; v1 += bb1; v2 += bb0; v3 += bb1;
            }
            if (r0 < M) { C[or0 * ldc + c0] = v0; C[or0 * ldc + c0 + 1] = v1; }
            if (r1 < M) { C[or1 * ldc + c0] = v2; C[or1 * ldc + c0 + 1] = v3; }
        }
    }
}

// ============ Phase B1: scores — one block per (s,b), chip-wide MUFU spread ============
__global__ void __launch_bounds__(128) k_scores(const float* __restrict__ Vw,
                                                const float* __restrict__ bq,
                                                const float* __restrict__ bV) {
    const int s = blockIdx.x, b = blockIdx.y;
    const int tid = threadIdx.x, lane = tid & 31, warp = tid >> 5;
    __shared__ float red[4];

    const float* kp = g_keys + ((size_t)b * S_ + s) * H_;
    float a = 0.f;
    for (int h = tid; h < H_; h += 128) {
        float q = bq[h];
#pragma unroll
        for (int ks = 0; ks < KS_; ks++) q += g_qA[(size_t)ks * B_ * NA_ + b * NA_ + h];
        a += tanhf(q + kp[h]) * Vw[h];
    }
#pragma unroll
    for (int o = 16; o; o >>= 1) a += __shfl_xor_sync(0xffffffffu, a, o);
    if (lane == 0) red[warp] = a;
    __syncthreads();
    if (tid == 0)
        g_scores[b * S_ + s] = red[0] + red[1] + red[2] + red[3] + bV[0];
}

// ============ Phase B2: softmax + attn output + ctx (32 blocks) ============
__global__ void __launch_bounds__(256) k_softctx(float* __restrict__ out_attn, int t) {
    __shared__ float ssc[48];
    const int b = blockIdx.x, tid = threadIdx.x;
    const int warp = tid >> 5, lane = tid & 31;

    if (warp == 0) {
        float v0 = g_scores[b * S_ + ((lane < S_) ? lane : 0)];
        if (lane >= S_) v0 = -INFINITY;
        float v1 = (lane < S_ - 32) ? g_scores[b * S_ + lane + 32] : -INFINITY;
        float m = fmaxf(v0, v1);
#pragma unroll
        for (int o = 16; o; o >>= 1) m = fmaxf(m, __shfl_xor_sync(0xffffffffu, m, o));
        float e0 = (lane < S_) ? expf(v0 - m) : 0.f;
        float e1 = (lane < S_ - 32) ? expf(v1 - m) : 0.f;
        float s = e0 + e1;
#pragma unroll
        for (int o = 16; o; o >>= 1) s += __shfl_xor_sync(0xffffffffu, s, o);
        float inv = 1.f / s;
        if (lane < S_) {
            float w0 = e0 * inv;
            ssc[lane] = w0;
            out_attn[((size_t)b * T_ + t) * S_ + lane] = w0;
        }
        if (lane < S_ - 32) {
            float w1 = e1 * inv;
            ssc[lane + 32] = w1;
            out_attn[((size_t)b * T_ + t) * S_ + lane + 32] = w1;
        }
    }
    __syncthreads();

    for (int h = tid; h < H_; h += 256) {
        const float* ep = g_encT + ((size_t)b * H_ + h) * S_;
        float a = 0.f;
#pragma unroll
        for (int s = 0; s < S_; s++) a += ssc[s] * ep[s];
        split_bf(a, g_ctxh_hi[b * 2048 + h], g_ctxh_lo[b * 2048 + h]);
    }
}

// ---------------- Phase C2: sum split-K partials + gpre + ghh, LSTM update ----------------
__global__ void __launch_bounds__(256) k_update2(int t) {
    const int tid = threadIdx.x;
    const int b = tid >> 3, jj = tid & 7;
    const int j = blockIdx.x * 8 + jj;
    const float* gpre = g_gates_pre + (size_t)t * B_ * G_ + (size_t)b * G_;

    float gate[4];
#pragma unroll
    for (int qc = 0; qc < 4; qc++) {
        int col = qc * 1024 + j;
        float v = gpre[col];
#pragma unroll
        for (int s = 0; s < KS_; s++) {
            v += g_gp[(size_t)s * B_ * G_ + (size_t)b * G_ + col];
            v += g_qA[(size_t)s * B_ * NA_ + b * NA_ + H_ + col];
        }
        gate[qc] = v;
    }

    float ig = 1.f / (1.f + expf(-gate[0]));
    float fg = 1.f / (1.f + expf(-gate[1]));
    float gg = tanhf(gate[2]);
    float og = 1.f / (1.f + expf(-gate[3]));
    int par = t & 1;
    int idx = b * H_ + j;
    float c = fg * g_c[par][idx] + ig * gg;
    float h = og * tanhf(c);
    g_c[par ^ 1][idx] = c;
    g_h[par ^ 1][idx] = h;
    split_bf(h, g_ctxh_hi[b * 2048 + H_ + j], g_ctxh_lo[b * 2048 + H_ + j]);
    g_Hbf[(size_t)(t * B_ + b) * H_ + j] = __float2bfloat16(h);
}

// ------------------------- in-place log-softmax over V per output row -------------------------
__global__ void __launch_bounds__(256) k_logsoftmax(float* __restrict__ out) {
    __shared__ float red[8];
    __shared__ float bc;
    const int r = blockIdx.x;
    float* x = out + OUT_DEC + (size_t)r * V_;
    const int tid = threadIdx.x, lane = tid & 31, warp = tid >> 5;

    float m = -INFINITY;
    for (int v = tid; v < V_; v += 256) m = fmaxf(m, x[v]);
#pragma unroll
    for (int o2 = 16; o2; o2 >>= 1) m = fmaxf(m, __shfl_xor_sync(0xffffffffu, m, o2));
    if (lane == 0) red[warp] = m;
    __syncthreads();
    if (tid == 0) {
        float mm = red[0];
#pragma unroll
        for (int w = 1; w < 8; w++) mm = fmaxf(mm, red[w]);
        bc = mm;
    }
    __syncthreads();
    m = bc;

    float s = 0.f;
    for (int v = tid; v < V_; v += 256) s += expf(x[v] - m);
#pragma unroll
    for (int o2 = 16; o2; o2 >>= 1) s += __shfl_xor_sync(0xffffffffu, s, o2);
    __syncthreads();
    if (lane == 0) red[warp] = s;
    __syncthreads();
    if (tid == 0) {
        float ss = 0.f;
#pragma unroll
        for (int w = 0; w < 8; w++) ss += red[w];
        bc = m + logf(ss);
    }
    __syncthreads();
    float ls = bc;

    for (int v = tid; v < V_; v += 256) x[v] -= ls;
}

// ------------------------- final state copy -------------------------
__global__ void __launch_bounds__(256) k_final(float* __restrict__ out) {
    int i = blockIdx.x * blockDim.x + threadIdx.x;
    if (i < B_ * H_) {
        out[OUT_HF + i] = g_h[1][i];
        out[OUT_CF + i] = g_c[1][i];
    }
}

// ------------------------- launch -------------------------
extern "C" void kernel_launch(void* const* d_in, const int* in_sizes, int n_in,
                              void* d_out, int out_size) {
    (void)in_sizes; (void)n_in; (void)out_size;
    const float* enc  = (const float*)d_in[0];
    const float* ehid = (const float*)d_in[1];
    const int*   tgt  = (const int*)d_in[2];
    const float* emb  = (const float*)d_in[3];
    const float* Wq   = (const float*)d_in[4];
    const float* bq   = (const float*)d_in[5];
    const float* Wk   = (const float*)d_in[6];
    const float* bk   = (const float*)d_in[7];
    const float* Vw   = (const float*)d_in[8];
    const float* bV   = (const float*)d_in[9];
    const float* Wih  = (const float*)d_in[10];
    const float* Whh  = (const float*)d_in[11];
    const float* bih  = (const float*)d_in[12];
    const float* bhh  = (const float*)d_in[13];
    const float* Wout = (const float*)d_in[14];
    const float* bout = (const float*)d_in[15];
    float* out = (float*)d_out;

    // opt-in to >48KB dynamic smem (idempotent; not an allocation)
    static bool attr_done = false;
    if (!attr_done) {
        cudaFuncSetAttribute((const void*)k_gemm_sm<true, false>,
                             cudaFuncAttributeMaxDynamicSharedMemorySize, SMEM_SPLIT);
        cudaFuncSetAttribute((const void*)k_gemm_sm<false, true>,
                             cudaFuncAttributeMaxDynamicSharedMemorySize, SMEM_SINGLE);
        attr_done = true;
    }

    void *p_enc_hi, *p_enc_lo, *p_Wk_hi, *p_Wk_lo, *p_Wqhh_hi, *p_Wqhh_lo,
         *p_Wx_hi, *p_Wx_lo, *p_Wc_hi, *p_Wc_lo, *p_Wout, *p_X_hi, *p_X_lo,
         *p_keys, *p_gpre, *p_qA, *p_gp, *p_ch_hi, *p_ch_lo, *p_Hbf, *p_bsum;
    cudaGetSymbolAddress(&p_enc_hi, g_enc_hi);
    cudaGetSymbolAddress(&p_enc_lo, g_enc_lo);
    cudaGetSymbolAddress(&p_Wk_hi, g_Wk_hi);
    cudaGetSymbolAddress(&p_Wk_lo, g_Wk_lo);
    cudaGetSymbolAddress(&p_Wqhh_hi, g_Wqhh_hi);
    cudaGetSymbolAddress(&p_Wqhh_lo, g_Wqhh_lo);
    cudaGetSymbolAddress(&p_Wx_hi, g_Wx_hi);
    cudaGetSymbolAddress(&p_Wx_lo, g_Wx_lo);
    cudaGetSymbolAddress(&p_Wc_hi, g_Wc_hi);
    cudaGetSymbolAddress(&p_Wc_lo, g_Wc_lo);
    cudaGetSymbolAddress(&p_Wout, g_Wout_bf);
    cudaGetSymbolAddress(&p_X_hi, g_X_hi);
    cudaGetSymbolAddress(&p_X_lo, g_X_lo);
    cudaGetSymbolAddress(&p_keys, g_keys);
    cudaGetSymbolAddress(&p_gpre, g_gates_pre);
    cudaGetSymbolAddress(&p_qA, g_qA);
    cudaGetSymbolAddress(&p_gp, g_gp);
    cudaGetSymbolAddress(&p_ch_hi, g_ctxh_hi);
    cudaGetSymbolAddress(&p_ch_lo, g_ctxh_lo);
    cudaGetSymbolAddress(&p_Hbf, g_Hbf);
    cudaGetSymbolAddress(&p_bsum, g_bsum);

    // prep: 2 launches
    k_prep<<<2048, 256>>>(enc, ehid, Wq, Wk, Wih, Whh, bih, bhh, Wout);
    k_gather<<<TB_, 256>>>(emb, tgt);

    // hoisted GEMMs (split precision, smem-tiled, no K-split)
    {   // keys_proj = enc @ Wk^T + bk : [1312,1024]
        dim3 grid((TB_ + 63) / 64, H_ / 128, 1);
        k_gemm_sm<true, false><<<grid, 256, SMEM_SPLIT>>>(
            (const bf16*)p_enc_hi, (const bf16*)p_enc_lo, H_,
            (const bf16*)p_Wk_hi, (const bf16*)p_Wk_lo, H_,
            (float*)p_keys, H_, bk, TB_, H_, H_, 0);
    }
    {   // gates_pre = X @ Wx^T + (bih+bhh) : [1312,4096]
        dim3 grid((TB_ + 63) / 64, G_ / 128, 1);
        k_gemm_sm<true, false><<<grid, 256, SMEM_SPLIT>>>(
            (const bf16*)p_X_hi, (const bf16*)p_X_lo, H_,
            (const bf16*)p_Wx_hi, (const bf16*)p_Wx_lo, H_,
            (float*)p_gpre, G_, (const float*)p_bsum, TB_, G_, H_, 0);
    }

    // sequential decode: 5 launches per step (split-K GEMMs fill the chip)
    for (int t = 0; t < T_; t++) {
        {   // qghh partials = h @ [Wq|Whh]^T : [32,5120], 4 K-slices -> 160 blocks
            dim3 grid(1, NA_ / 128, KS_);
            k_gemm_sm<true, false><<<grid, 256, SMEM_SPLIT>>>(
                (const bf16*)p_ch_hi + H_, (const bf16*)p_ch_lo + H_, 2 * H_,
                (const bf16*)p_Wqhh_hi, (const bf16*)p_Wqhh_lo, H_,
                (float*)p_qA, NA_, nullptr, B_, NA_, KC_, (size_t)B_ * NA_);
        }
        k_scores<<<dim3(S_, B_), 128>>>(Vw, bq, bV);
        k_softctx<<<B_, 256>>>(out + OUT_ATTN, t);
        {   // gates_ctx partials = ctx @ Wc^T : [32,4096], 4 K-slices -> 128 blocks
            dim3 grid(1, G_ / 128, KS_);
            k_gemm_sm<true, false><<<grid, 256, SMEM_SPLIT>>>(
                (const bf16*)p_ch_hi, (const bf16*)p_ch_lo, 2 * H_,
                (const bf16*)p_Wc_hi, (const bf16*)p_Wc_lo, H_,
                (float*)p_gp, G_, nullptr, B_, G_, KC_, (size_t)B_ * G_);
        }
        k_update2<<<128, 256>>>(t);
    }

    {   // logits -> directly into out[OUT_DEC] at [b,t,:] via remap epilogue (single bf16)
        dim3 grid((TB_ + 63) / 64, V_ / 128, 1);
        k_gemm_sm<false, true><<<grid, 256, SMEM_SINGLE>>>(
            (const bf16*)p_Hbf, nullptr, H_,
            (const bf16*)p_Wout, nullptr, H_,
            out + OUT_DEC, V_, bout, TB_, V_, H_, 0);
    }
    k_logsoftmax<<<TB_, 256>>>(out);
    k_final<<<128, 256>>>(out);
}